// round 7
// baseline (speedup 1.0000x reference)
#include <cuda_runtime.h>
#include <cuda_bf16.h>
#include <cstdint>
#include <cstddef>
#include <math.h>

// ---------------- problem dims ----------------
#define BB 4096
#define HH 2048
#define K1 6144          // K for GEMM1: [x|h|c]
#define N1 8192          // N for GEMM1: 4 gates * 2048

// ---------------- GEMM tile config ----------------
#define BM 128
#define BN 256
#define BK 32            // bf16 elements per chunk
#define LDT 40           // smem row stride in bf16 (80 bytes: 64 data + 16 pad)
#define A_TILE_BYTES (BM * LDT * 2)          // 10240
#define B_TILE_BYTES (BN * LDT * 2)          // 20480
#define ST_AH 0
#define ST_AL A_TILE_BYTES
#define ST_BH (2 * A_TILE_BYTES)
#define ST_BL (2 * A_TILE_BYTES + B_TILE_BYTES)
#define STAGE_BYTES (2 * A_TILE_BYTES + 2 * B_TILE_BYTES)   // 61440
#define NSTAGE 3
#define SMEM_DYN (NSTAGE * STAGE_BYTES + 128)

// ---------------- device scratch (static; alloc APIs are forbidden) ------
__device__ __nv_bfloat16 g_A1hi[(size_t)BB * K1];
__device__ __nv_bfloat16 g_A1lo[(size_t)BB * K1];
__device__ __nv_bfloat16 g_W1hi[(size_t)N1 * K1];
__device__ __nv_bfloat16 g_W1lo[(size_t)N1 * K1];
__device__ __nv_bfloat16 g_W2hi[(size_t)HH * HH];
__device__ __nv_bfloat16 g_W2lo[(size_t)HH * HH];
__device__ __nv_bfloat16 g_A2hi[(size_t)BB * HH];
__device__ __nv_bfloat16 g_A2lo[(size_t)BB * HH];
__device__ float         g_C[(size_t)BB * N1];

// ---------------- helpers ----------------
__device__ __forceinline__ uint32_t smem_u32(const void* p) {
    uint32_t a;
    asm("{ .reg .u64 t; cvta.to.shared.u64 t, %1; cvt.u32.u64 %0, t; }" : "=r"(a) : "l"(p));
    return a;
}

__device__ __forceinline__ void cp_async16(uint32_t dst, const void* src) {
    asm volatile("cp.async.cg.shared.global [%0], [%1], 16;" :: "r"(dst), "l"(src));
}

__device__ __forceinline__ void ldmatrix_x4(uint32_t* r, uint32_t addr) {
    asm volatile("ldmatrix.sync.aligned.m8n8.x4.shared.b16 {%0,%1,%2,%3}, [%4];"
        : "=r"(r[0]), "=r"(r[1]), "=r"(r[2]), "=r"(r[3]) : "r"(addr));
}

__device__ __forceinline__ uint32_t lds32(uint32_t addr) {
    uint32_t v;
    asm volatile("ld.shared.b32 %0, [%1];" : "=r"(v) : "r"(addr));
    return v;
}

__device__ __forceinline__ void mma_16816(float* c, const uint32_t* a, const uint32_t* b) {
    asm volatile(
        "mma.sync.aligned.m16n8k16.row.col.f32.bf16.bf16.f32 "
        "{%0,%1,%2,%3}, {%4,%5,%6,%7}, {%8,%9}, {%0,%1,%2,%3};"
        : "+f"(c[0]), "+f"(c[1]), "+f"(c[2]), "+f"(c[3])
        : "r"(a[0]), "r"(a[1]), "r"(a[2]), "r"(a[3]), "r"(b[0]), "r"(b[1]));
}

__device__ __forceinline__ void split_store(__nv_bfloat16* hi, __nv_bfloat16* lo,
                                            size_t i, float v) {
    __nv_bfloat16 h = __float2bfloat16(v);
    hi[i] = h;
    lo[i] = __float2bfloat16(v - __bfloat162float(h));
}

// ---------------- packing kernels ----------------
__global__ void pack_A1(const float* __restrict__ x, const float* __restrict__ h,
                        const float* __restrict__ c) {
    size_t n = (size_t)BB * K1;
    for (size_t i = blockIdx.x * (size_t)blockDim.x + threadIdx.x; i < n;
         i += (size_t)gridDim.x * blockDim.x) {
        size_t m = i / K1;
        int k = (int)(i - m * K1);
        float v;
        if (k < HH)          v = x[m * HH + k];
        else if (k < 2 * HH) v = h[m * HH + (k - HH)];
        else                 v = c[m * HH + (k - 2 * HH)];
        split_store(g_A1hi, g_A1lo, i, v);
    }
}

__global__ void pack_W1(const float* __restrict__ Wix, const float* __restrict__ Wfx,
                        const float* __restrict__ Wcx, const float* __restrict__ Wox,
                        const float* __restrict__ Wih, const float* __restrict__ Wic,
                        const float* __restrict__ Wfh, const float* __restrict__ Wfc,
                        const float* __restrict__ Wch, const float* __restrict__ Woh) {
    size_t n = (size_t)N1 * K1;
    for (size_t i = blockIdx.x * (size_t)blockDim.x + threadIdx.x; i < n;
         i += (size_t)gridDim.x * blockDim.x) {
        size_t row = i / K1;
        int k = (int)(i - row * K1);
        int gate = (int)(row >> 11);
        int j = (int)(row & 2047);
        int seg = k >> 11;
        int kk = k & 2047;
        const float* W = nullptr;
        switch (gate * 3 + seg) {
            case 0:  W = Wix; break;
            case 1:  W = Wih; break;
            case 2:  W = Wic; break;
            case 3:  W = Wfx; break;
            case 4:  W = Wfh; break;
            case 5:  W = Wfc; break;
            case 6:  W = Wcx; break;
            case 7:  W = Wch; break;
            case 9:  W = Wox; break;
            case 10: W = Woh; break;
            default: break;   // gate g/o c-slot: zero (never read: variable-K skips it)
        }
        float v = W ? W[(size_t)j * HH + kk] : 0.0f;
        split_store(g_W1hi, g_W1lo, i, v);
    }
}

__global__ void pack_W2(const float* __restrict__ Woc) {
    size_t n = (size_t)HH * HH;
    for (size_t i = blockIdx.x * (size_t)blockDim.x + threadIdx.x; i < n;
         i += (size_t)gridDim.x * blockDim.x) {
        split_store(g_W2hi, g_W2lo, i, Woc[i]);
    }
}

// ---------------- GEMM: C = Ahi*Bhi^T + Ahi*Blo^T + Alo*Bhi^T ---------------
// sm80-style: cp.async 3-stage pipeline + mma.sync m16n8k16 bf16.
// CTA tile 128x256, 8 warps as 2(M) x 4(N), warp tile 64x64.
// MMA schedule: ni processed in pairs; within a pair, each pass issues
// 8 independent MMAs (4 mi x 2 ni) -> RAW distance 8 on every accumulator.
__global__ void __launch_bounds__(256, 1)
gemm_kernel(int which) {
    const __nv_bfloat16 *Ahi, *Alo, *Bhi, *Blo;
    float* C;
    int K, Keff;
    const size_t brow0 = (size_t)blockIdx.y * BN;
    if (which == 0) {
        Ahi = g_A1hi; Alo = g_A1lo; Bhi = g_W1hi; Blo = g_W1lo;
        C = g_C; K = K1;
        Keff = (brow0 >= 4096) ? 4096 : 6144;   // gates g,o have zero c-slot
    } else {
        Ahi = g_A2hi; Alo = g_A2lo; Bhi = g_W2hi; Blo = g_W2lo;
        C = g_C + 2 * HH;   // gate-g column region (already consumed by ew1)
        K = HH; Keff = HH;
    }
    const int ldc = N1;
    const size_t arow0 = (size_t)blockIdx.x * BM;
    const int nchunk = Keff / BK;
    const int tid = threadIdx.x;
    const int lane = tid & 31;
    const int wid = tid >> 5;
    const int warpM = wid & 1;   // 2 warps over M: 64 rows each
    const int warpN = wid >> 1;  // 4 warps over N: 64 cols each

    extern __shared__ char dsmem[];
    const uint32_t sb = (smem_u32(dsmem) + 127u) & ~127u;

    // loader for chunk j into stage s (always commits, possibly empty group)
    auto load_chunk = [&](int j, int s) {
        if (j < nchunk) {
            const uint32_t stage = sb + s * STAGE_BYTES;
            const size_t kof = (size_t)j * BK;
            #pragma unroll
            for (int it = 0; it < 12; ++it) {
                int idx = tid + it * 256;        // 0..3071
                int g = idx & 3;                 // 16B segment within 64B row
                int rs = idx >> 2;               // 0..767: tile-row id
                const __nv_bfloat16* src;
                uint32_t dstbase;
                int r;
                if (rs < 128)      { r = rs;       src = Ahi + (arow0 + r) * K + kof; dstbase = stage + ST_AH; }
                else if (rs < 256) { r = rs - 128; src = Alo + (arow0 + r) * K + kof; dstbase = stage + ST_AL; }
                else if (rs < 512) { r = rs - 256; src = Bhi + (brow0 + r) * K + kof; dstbase = stage + ST_BH; }
                else               { r = rs - 512; src = Blo + (brow0 + r) * K + kof; dstbase = stage + ST_BL; }
                uint32_t dst = dstbase + (uint32_t)r * (LDT * 2) + (uint32_t)g * 16u;
                cp_async16(dst, (const void*)(src + g * 8));
            }
        }
        asm volatile("cp.async.commit_group;" ::: "memory");
    };

    float acc[4][8][4];
    #pragma unroll
    for (int mi = 0; mi < 4; ++mi)
        #pragma unroll
        for (int ni = 0; ni < 8; ++ni)
            #pragma unroll
            for (int q = 0; q < 4; ++q) acc[mi][ni][q] = 0.0f;

    load_chunk(0, 0);
    load_chunk(1, 1);

    for (int j = 0; j < nchunk; ++j) {
        const int s = j % NSTAGE;
        asm volatile("cp.async.wait_group 1;" ::: "memory");
        __syncthreads();
        load_chunk(j + 2, (j + 2) % NSTAGE);

        const uint32_t stage = sb + s * STAGE_BYTES;
        const uint32_t a_hi = stage + ST_AH + (warpM * 64 + (lane & 15)) * (LDT * 2) + (lane >> 4) * 16;
        const uint32_t a_lo = stage + ST_AL + (warpM * 64 + (lane & 15)) * (LDT * 2) + (lane >> 4) * 16;
        const uint32_t b_hi0 = stage + ST_BH + (warpN * 64 + (lane >> 2)) * (LDT * 2) + (lane & 3) * 4;
        const uint32_t b_lo0 = stage + ST_BL + (warpN * 64 + (lane >> 2)) * (LDT * 2) + (lane & 3) * 4;

        #pragma unroll
        for (int ks = 0; ks < 2; ++ks) {     // two k16 steps per BK=32 chunk
            const uint32_t koff = ks * 32;   // 16 bf16 = 32 bytes
            uint32_t ah[4][4], al[4][4];
            #pragma unroll
            for (int mi = 0; mi < 4; ++mi) {
                ldmatrix_x4(ah[mi], a_hi + mi * 16 * (LDT * 2) + koff);
                ldmatrix_x4(al[mi], a_lo + mi * 16 * (LDT * 2) + koff);
            }
            #pragma unroll
            for (int np = 0; np < 4; ++np) {
                const int ni0 = np * 2, ni1 = np * 2 + 1;
                uint32_t bh0[2], bh1[2], bl0[2], bl1[2];
                const uint32_t bro0 = ni0 * 8 * (LDT * 2) + koff;
                const uint32_t bro1 = ni1 * 8 * (LDT * 2) + koff;
                bh0[0] = lds32(b_hi0 + bro0);      bh0[1] = lds32(b_hi0 + bro0 + 16);
                bh1[0] = lds32(b_hi0 + bro1);      bh1[1] = lds32(b_hi0 + bro1 + 16);
                bl0[0] = lds32(b_lo0 + bro0);      bl0[1] = lds32(b_lo0 + bro0 + 16);
                bl1[0] = lds32(b_lo0 + bro1);      bl1[1] = lds32(b_lo0 + bro1 + 16);
                // pass 1: Ahi * Bhi  (8 independent MMAs)
                #pragma unroll
                for (int mi = 0; mi < 4; ++mi) mma_16816(acc[mi][ni0], ah[mi], bh0);
                #pragma unroll
                for (int mi = 0; mi < 4; ++mi) mma_16816(acc[mi][ni1], ah[mi], bh1);
                // pass 2: Ahi * Blo
                #pragma unroll
                for (int mi = 0; mi < 4; ++mi) mma_16816(acc[mi][ni0], ah[mi], bl0);
                #pragma unroll
                for (int mi = 0; mi < 4; ++mi) mma_16816(acc[mi][ni1], ah[mi], bl1);
                // pass 3: Alo * Bhi
                #pragma unroll
                for (int mi = 0; mi < 4; ++mi) mma_16816(acc[mi][ni0], al[mi], bh0);
                #pragma unroll
                for (int mi = 0; mi < 4; ++mi) mma_16816(acc[mi][ni1], al[mi], bh1);
            }
        }
        __syncthreads();
    }

    // epilogue: fp32 store
    #pragma unroll
    for (int mi = 0; mi < 4; ++mi) {
        const size_t m0 = arow0 + warpM * 64 + mi * 16 + (lane >> 2);
        #pragma unroll
        for (int ni = 0; ni < 8; ++ni) {
            const size_t n0 = brow0 + warpN * 64 + ni * 8 + (lane & 3) * 2;
            float2 v0 = make_float2(acc[mi][ni][0], acc[mi][ni][1]);
            float2 v1 = make_float2(acc[mi][ni][2], acc[mi][ni][3]);
            *reinterpret_cast<float2*>(C + m0 * ldc + n0)       = v0;
            *reinterpret_cast<float2*>(C + (m0 + 8) * ldc + n0) = v1;
        }
    }
}

// ---------------- elementwise 1: gates i,f,g -> c_next; pack A2 -------------
__global__ void ew1(const float* __restrict__ c,
                    const float* __restrict__ b_ix, const float* __restrict__ b_ih,
                    const float* __restrict__ b_ic,
                    const float* __restrict__ b_fx, const float* __restrict__ b_fh,
                    const float* __restrict__ b_fc,
                    const float* __restrict__ b_cx, const float* __restrict__ b_ch,
                    float* __restrict__ out) {
    const size_t n = (size_t)BB * HH;
    for (size_t i = blockIdx.x * (size_t)blockDim.x + threadIdx.x; i < n;
         i += (size_t)gridDim.x * blockDim.x) {
        size_t m = i / HH;
        int j = (int)(i - m * HH);
        const float* crow = g_C + m * (size_t)N1;
        float ip = crow[j]        + b_ix[j] + b_ih[j] + b_ic[j];
        float fp = crow[2048 + j] + b_fx[j] + b_fh[j] + b_fc[j];
        float gp = crow[4096 + j] + b_cx[j] + b_ch[j];
        float ii = 1.0f / (1.0f + expf(-ip));
        float ff = 1.0f / (1.0f + expf(-fp));
        float gg = tanhf(gp);
        float cn = ff * c[i] + ii * gg;
        out[2 * n + i] = cn;                       // c_next
        split_store(g_A2hi, g_A2lo, i, cn);        // A2 for GEMM2
    }
}

// ---------------- elementwise 2: o gate, h_next ----------------
__global__ void ew2(const float* __restrict__ b_ox, const float* __restrict__ b_oh,
                    const float* __restrict__ b_oc,
                    float* __restrict__ out) {
    const size_t n = (size_t)BB * HH;
    for (size_t i = blockIdx.x * (size_t)blockDim.x + threadIdx.x; i < n;
         i += (size_t)gridDim.x * blockDim.x) {
        size_t m = i / HH;
        int j = (int)(i - m * HH);
        const float* crow = g_C + m * (size_t)N1;
        float op = crow[6144 + j] + crow[4096 + j] + b_ox[j] + b_oh[j] + b_oc[j];
        float cn = out[2 * n + i];
        float t = tanhf(cn);
        float o = (1.0f / (1.0f + expf(-op))) * t;
        out[i] = o;           // o
        out[n + i] = o * t;   // h_next
    }
}

// ---------------- launch ----------------
extern "C" void kernel_launch(void* const* d_in, const int* in_sizes, int n_in,
                              void* d_out, int out_size) {
    const float* x    = (const float*)d_in[0];
    const float* h    = (const float*)d_in[1];
    const float* c    = (const float*)d_in[2];
    const float* W_ix = (const float*)d_in[3];
    const float* b_ix = (const float*)d_in[4];
    const float* W_fx = (const float*)d_in[5];
    const float* b_fx = (const float*)d_in[6];
    const float* W_cx = (const float*)d_in[7];
    const float* b_cx = (const float*)d_in[8];
    const float* W_ox = (const float*)d_in[9];
    const float* b_ox = (const float*)d_in[10];
    const float* W_ih = (const float*)d_in[11];
    const float* b_ih = (const float*)d_in[12];
    const float* W_ic = (const float*)d_in[13];
    const float* b_ic = (const float*)d_in[14];
    const float* W_fh = (const float*)d_in[15];
    const float* b_fh = (const float*)d_in[16];
    const float* W_fc = (const float*)d_in[17];
    const float* b_fc = (const float*)d_in[18];
    const float* W_ch = (const float*)d_in[19];
    const float* b_ch = (const float*)d_in[20];
    const float* W_oh = (const float*)d_in[21];
    const float* b_oh = (const float*)d_in[22];
    const float* W_oc = (const float*)d_in[23];
    const float* b_oc = (const float*)d_in[24];
    float* out = (float*)d_out;

    static int attr_done = 0;
    if (!attr_done) {
        cudaFuncSetAttribute(gemm_kernel, cudaFuncAttributeMaxDynamicSharedMemorySize, SMEM_DYN);
        attr_done = 1;
    }

    pack_A1<<<2048, 256>>>(x, h, c);
    pack_W1<<<8192, 256>>>(W_ix, W_fx, W_cx, W_ox, W_ih, W_ic, W_fh, W_fc, W_ch, W_oh);
    pack_W2<<<1024, 256>>>(W_oc);

    dim3 g1(BB / BM, N1 / BN);   // 32 x 32
    gemm_kernel<<<g1, 256, SMEM_DYN>>>(0);

    ew1<<<4096, 256>>>(c, b_ix, b_ih, b_ic, b_fx, b_fh, b_fc, b_cx, b_ch, out);

    dim3 g2(BB / BM, HH / BN);   // 32 x 8
    gemm_kernel<<<g2, 256, SMEM_DYN>>>(1);

    ew2<<<4096, 256>>>(b_ox, b_oh, b_oc, out);
}

// round 8
// speedup vs baseline: 1.1238x; 1.1238x over previous
#include <cuda_runtime.h>
#include <cuda_bf16.h>
#include <cstdint>
#include <cstddef>
#include <math.h>

// ---------------- problem dims ----------------
#define BB 4096
#define HH 2048
#define K1 6144          // K for GEMM1: [x|h|c]
#define N1 8192          // N for GEMM1: 4 gates * 2048

// ---------------- GEMM tile config ----------------
#define BM 128
#define BN 256
#define BK 64            // bf16 elements per chunk (128B data per row)
#define ROWB 144         // smem row stride bytes (128 data + 16 pad)
#define A_TILE_BYTES (BM * ROWB)             // 18432
#define B_TILE_BYTES (BN * ROWB)             // 36864
#define ST_AH 0
#define ST_AL A_TILE_BYTES
#define ST_BH (2 * A_TILE_BYTES)
#define ST_BL (2 * A_TILE_BYTES + B_TILE_BYTES)
#define STAGE_BYTES (2 * A_TILE_BYTES + 2 * B_TILE_BYTES)   // 110592
#define NSTAGE 2
#define SMEM_DYN (NSTAGE * STAGE_BYTES + 128)               // 221312

// ---------------- device scratch (static; alloc APIs are forbidden) ------
__device__ __nv_bfloat16 g_A1hi[(size_t)BB * K1];
__device__ __nv_bfloat16 g_A1lo[(size_t)BB * K1];
__device__ __nv_bfloat16 g_W1hi[(size_t)N1 * K1];
__device__ __nv_bfloat16 g_W1lo[(size_t)N1 * K1];
__device__ __nv_bfloat16 g_W2hi[(size_t)HH * HH];
__device__ __nv_bfloat16 g_W2lo[(size_t)HH * HH];
__device__ __nv_bfloat16 g_A2hi[(size_t)BB * HH];
__device__ __nv_bfloat16 g_A2lo[(size_t)BB * HH];
__device__ float         g_C[(size_t)BB * N1];

// ---------------- helpers ----------------
__device__ __forceinline__ uint32_t smem_u32(const void* p) {
    uint32_t a;
    asm("{ .reg .u64 t; cvta.to.shared.u64 t, %1; cvt.u32.u64 %0, t; }" : "=r"(a) : "l"(p));
    return a;
}

__device__ __forceinline__ void cp_async16(uint32_t dst, const void* src) {
    asm volatile("cp.async.cg.shared.global [%0], [%1], 16;" :: "r"(dst), "l"(src));
}

__device__ __forceinline__ void ldmatrix_x4(uint32_t* r, uint32_t addr) {
    asm volatile("ldmatrix.sync.aligned.m8n8.x4.shared.b16 {%0,%1,%2,%3}, [%4];"
        : "=r"(r[0]), "=r"(r[1]), "=r"(r[2]), "=r"(r[3]) : "r"(addr));
}

__device__ __forceinline__ uint32_t lds32(uint32_t addr) {
    uint32_t v;
    asm volatile("ld.shared.b32 %0, [%1];" : "=r"(v) : "r"(addr));
    return v;
}

__device__ __forceinline__ void mma_16816(float* c, const uint32_t* a, const uint32_t* b) {
    asm volatile(
        "mma.sync.aligned.m16n8k16.row.col.f32.bf16.bf16.f32 "
        "{%0,%1,%2,%3}, {%4,%5,%6,%7}, {%8,%9}, {%0,%1,%2,%3};"
        : "+f"(c[0]), "+f"(c[1]), "+f"(c[2]), "+f"(c[3])
        : "r"(a[0]), "r"(a[1]), "r"(a[2]), "r"(a[3]), "r"(b[0]), "r"(b[1]));
}

__device__ __forceinline__ void split_store(__nv_bfloat16* hi, __nv_bfloat16* lo,
                                            size_t i, float v) {
    __nv_bfloat16 h = __float2bfloat16(v);
    hi[i] = h;
    lo[i] = __float2bfloat16(v - __bfloat162float(h));
}

// ---------------- packing kernels ----------------
__global__ void pack_A1(const float* __restrict__ x, const float* __restrict__ h,
                        const float* __restrict__ c) {
    size_t n = (size_t)BB * K1;
    for (size_t i = blockIdx.x * (size_t)blockDim.x + threadIdx.x; i < n;
         i += (size_t)gridDim.x * blockDim.x) {
        size_t m = i / K1;
        int k = (int)(i - m * K1);
        float v;
        if (k < HH)          v = x[m * HH + k];
        else if (k < 2 * HH) v = h[m * HH + (k - HH)];
        else                 v = c[m * HH + (k - 2 * HH)];
        split_store(g_A1hi, g_A1lo, i, v);
    }
}

__global__ void pack_W1(const float* __restrict__ Wix, const float* __restrict__ Wfx,
                        const float* __restrict__ Wcx, const float* __restrict__ Wox,
                        const float* __restrict__ Wih, const float* __restrict__ Wic,
                        const float* __restrict__ Wfh, const float* __restrict__ Wfc,
                        const float* __restrict__ Wch, const float* __restrict__ Woh) {
    size_t n = (size_t)N1 * K1;
    for (size_t i = blockIdx.x * (size_t)blockDim.x + threadIdx.x; i < n;
         i += (size_t)gridDim.x * blockDim.x) {
        size_t row = i / K1;
        int k = (int)(i - row * K1);
        int gate = (int)(row >> 11);
        int j = (int)(row & 2047);
        int seg = k >> 11;
        int kk = k & 2047;
        const float* W = nullptr;
        switch (gate * 3 + seg) {
            case 0:  W = Wix; break;
            case 1:  W = Wih; break;
            case 2:  W = Wic; break;
            case 3:  W = Wfx; break;
            case 4:  W = Wfh; break;
            case 5:  W = Wfc; break;
            case 6:  W = Wcx; break;
            case 7:  W = Wch; break;
            case 9:  W = Wox; break;
            case 10: W = Woh; break;
            default: break;   // gate g/o c-slot: zero (never read: variable-K skips it)
        }
        float v = W ? W[(size_t)j * HH + kk] : 0.0f;
        split_store(g_W1hi, g_W1lo, i, v);
    }
}

__global__ void pack_W2(const float* __restrict__ Woc) {
    size_t n = (size_t)HH * HH;
    for (size_t i = blockIdx.x * (size_t)blockDim.x + threadIdx.x; i < n;
         i += (size_t)gridDim.x * blockDim.x) {
        split_store(g_W2hi, g_W2lo, i, Woc[i]);
    }
}

// ---------------- GEMM: C = Ahi*Bhi^T + Ahi*Blo^T + Alo*Bhi^T ---------------
// cp.async 2-stage pipeline, BK=64, ONE barrier + ONE wait per chunk.
// CTA tile 128x256, 8 warps as 2(M) x 4(N), warp tile 64x64.
__global__ void __launch_bounds__(256, 1)
gemm_kernel(int which) {
    const __nv_bfloat16 *Ahi, *Alo, *Bhi, *Blo;
    float* C;
    int K, Keff;
    const size_t brow0 = (size_t)blockIdx.y * BN;
    if (which == 0) {
        Ahi = g_A1hi; Alo = g_A1lo; Bhi = g_W1hi; Blo = g_W1lo;
        C = g_C; K = K1;
        Keff = (brow0 >= 4096) ? 4096 : 6144;   // gates g,o have zero c-slot
    } else {
        Ahi = g_A2hi; Alo = g_A2lo; Bhi = g_W2hi; Blo = g_W2lo;
        C = g_C + 2 * HH;   // gate-g column region (already consumed by ew1)
        K = HH; Keff = HH;
    }
    const int ldc = N1;
    const size_t arow0 = (size_t)blockIdx.x * BM;
    const int nchunk = Keff / BK;
    const int tid = threadIdx.x;
    const int lane = tid & 31;
    const int wid = tid >> 5;
    const int warpM = wid & 1;   // 2 warps over M: 64 rows each
    const int warpN = wid >> 1;  // 4 warps over N: 64 cols each

    extern __shared__ char dsmem[];
    const uint32_t sb = (smem_u32(dsmem) + 127u) & ~127u;

    // loader for chunk j into stage s (always commits, possibly empty group)
    auto load_chunk = [&](int j, int s) {
        if (j < nchunk) {
            const uint32_t stage = sb + s * STAGE_BYTES;
            const size_t kof = (size_t)j * BK;
            #pragma unroll
            for (int it = 0; it < 24; ++it) {
                int idx = tid + it * 256;        // 0..6143
                int g = idx & 7;                 // 16B segment within 128B row
                int rs = idx >> 3;               // 0..767: tile-row id
                const __nv_bfloat16* src;
                uint32_t dstbase;
                int r;
                if (rs < 128)      { r = rs;       src = Ahi + (arow0 + r) * K + kof; dstbase = stage + ST_AH; }
                else if (rs < 256) { r = rs - 128; src = Alo + (arow0 + r) * K + kof; dstbase = stage + ST_AL; }
                else if (rs < 512) { r = rs - 256; src = Bhi + (brow0 + r) * K + kof; dstbase = stage + ST_BH; }
                else               { r = rs - 512; src = Blo + (brow0 + r) * K + kof; dstbase = stage + ST_BL; }
                uint32_t dst = dstbase + (uint32_t)r * ROWB + (uint32_t)g * 16u;
                cp_async16(dst, (const void*)(src + g * 8));
            }
        }
        asm volatile("cp.async.commit_group;" ::: "memory");
    };

    float acc[4][8][4];
    #pragma unroll
    for (int mi = 0; mi < 4; ++mi)
        #pragma unroll
        for (int ni = 0; ni < 8; ++ni)
            #pragma unroll
            for (int q = 0; q < 4; ++q) acc[mi][ni][q] = 0.0f;

    load_chunk(0, 0);

    for (int j = 0; j < nchunk; ++j) {
        const int s = j & 1;
        // wait for chunk j's data, single barrier, then prefetch j+1 into s^1.
        asm volatile("cp.async.wait_group 0;" ::: "memory");
        __syncthreads();          // all warps see chunk j; all done reading s^1 (iter j-1)
        load_chunk(j + 1, s ^ 1);

        const uint32_t stage = sb + s * STAGE_BYTES;
        const uint32_t a_hi = stage + ST_AH + (warpM * 64 + (lane & 15)) * ROWB + (lane >> 4) * 16;
        const uint32_t a_lo = stage + ST_AL + (warpM * 64 + (lane & 15)) * ROWB + (lane >> 4) * 16;
        const uint32_t b_hi0 = stage + ST_BH + (warpN * 64 + (lane >> 2)) * ROWB + (lane & 3) * 4;
        const uint32_t b_lo0 = stage + ST_BL + (warpN * 64 + (lane >> 2)) * ROWB + (lane & 3) * 4;

        #pragma unroll
        for (int ks = 0; ks < 4; ++ks) {     // four k16 steps per BK=64 chunk
            const uint32_t koff = ks * 32;   // 16 bf16 = 32 bytes
            uint32_t ah[4][4], al[4][4];
            #pragma unroll
            for (int mi = 0; mi < 4; ++mi) {
                ldmatrix_x4(ah[mi], a_hi + mi * 16 * ROWB + koff);
                ldmatrix_x4(al[mi], a_lo + mi * 16 * ROWB + koff);
            }
            #pragma unroll
            for (int np = 0; np < 4; ++np) {
                const int ni0 = np * 2, ni1 = np * 2 + 1;
                uint32_t bh0[2], bh1[2], bl0[2], bl1[2];
                const uint32_t bro0 = ni0 * 8 * ROWB + koff;
                const uint32_t bro1 = ni1 * 8 * ROWB + koff;
                bh0[0] = lds32(b_hi0 + bro0);      bh0[1] = lds32(b_hi0 + bro0 + 16);
                bh1[0] = lds32(b_hi0 + bro1);      bh1[1] = lds32(b_hi0 + bro1 + 16);
                bl0[0] = lds32(b_lo0 + bro0);      bl0[1] = lds32(b_lo0 + bro0 + 16);
                bl1[0] = lds32(b_lo0 + bro1);      bl1[1] = lds32(b_lo0 + bro1 + 16);
                #pragma unroll
                for (int mi = 0; mi < 4; ++mi) mma_16816(acc[mi][ni0], ah[mi], bh0);
                #pragma unroll
                for (int mi = 0; mi < 4; ++mi) mma_16816(acc[mi][ni1], ah[mi], bh1);
                #pragma unroll
                for (int mi = 0; mi < 4; ++mi) mma_16816(acc[mi][ni0], ah[mi], bl0);
                #pragma unroll
                for (int mi = 0; mi < 4; ++mi) mma_16816(acc[mi][ni1], ah[mi], bl1);
                #pragma unroll
                for (int mi = 0; mi < 4; ++mi) mma_16816(acc[mi][ni0], al[mi], bh0);
                #pragma unroll
                for (int mi = 0; mi < 4; ++mi) mma_16816(acc[mi][ni1], al[mi], bh1);
            }
        }
    }

    // epilogue: fp32 store
    #pragma unroll
    for (int mi = 0; mi < 4; ++mi) {
        const size_t m0 = arow0 + warpM * 64 + mi * 16 + (lane >> 2);
        #pragma unroll
        for (int ni = 0; ni < 8; ++ni) {
            const size_t n0 = brow0 + warpN * 64 + ni * 8 + (lane & 3) * 2;
            float2 v0 = make_float2(acc[mi][ni][0], acc[mi][ni][1]);
            float2 v1 = make_float2(acc[mi][ni][2], acc[mi][ni][3]);
            *reinterpret_cast<float2*>(C + m0 * ldc + n0)       = v0;
            *reinterpret_cast<float2*>(C + (m0 + 8) * ldc + n0) = v1;
        }
    }
}

// ---------------- elementwise 1: gates i,f,g -> c_next; pack A2 -------------
__global__ void ew1(const float* __restrict__ c,
                    const float* __restrict__ b_ix, const float* __restrict__ b_ih,
                    const float* __restrict__ b_ic,
                    const float* __restrict__ b_fx, const float* __restrict__ b_fh,
                    const float* __restrict__ b_fc,
                    const float* __restrict__ b_cx, const float* __restrict__ b_ch,
                    float* __restrict__ out) {
    const size_t n = (size_t)BB * HH;
    for (size_t i = blockIdx.x * (size_t)blockDim.x + threadIdx.x; i < n;
         i += (size_t)gridDim.x * blockDim.x) {
        size_t m = i / HH;
        int j = (int)(i - m * HH);
        const float* crow = g_C + m * (size_t)N1;
        float ip = crow[j]        + b_ix[j] + b_ih[j] + b_ic[j];
        float fp = crow[2048 + j] + b_fx[j] + b_fh[j] + b_fc[j];
        float gp = crow[4096 + j] + b_cx[j] + b_ch[j];
        float ii = 1.0f / (1.0f + expf(-ip));
        float ff = 1.0f / (1.0f + expf(-fp));
        float gg = tanhf(gp);
        float cn = ff * c[i] + ii * gg;
        out[2 * n + i] = cn;                       // c_next
        split_store(g_A2hi, g_A2lo, i, cn);        // A2 for GEMM2
    }
}

// ---------------- elementwise 2: o gate, h_next ----------------
__global__ void ew2(const float* __restrict__ b_ox, const float* __restrict__ b_oh,
                    const float* __restrict__ b_oc,
                    float* __restrict__ out) {
    const size_t n = (size_t)BB * HH;
    for (size_t i = blockIdx.x * (size_t)blockDim.x + threadIdx.x; i < n;
         i += (size_t)gridDim.x * blockDim.x) {
        size_t m = i / HH;
        int j = (int)(i - m * HH);
        const float* crow = g_C + m * (size_t)N1;
        float op = crow[6144 + j] + crow[4096 + j] + b_ox[j] + b_oh[j] + b_oc[j];
        float cn = out[2 * n + i];
        float t = tanhf(cn);
        float o = (1.0f / (1.0f + expf(-op))) * t;
        out[i] = o;           // o
        out[n + i] = o * t;   // h_next
    }
}

// ---------------- launch ----------------
extern "C" void kernel_launch(void* const* d_in, const int* in_sizes, int n_in,
                              void* d_out, int out_size) {
    const float* x    = (const float*)d_in[0];
    const float* h    = (const float*)d_in[1];
    const float* c    = (const float*)d_in[2];
    const float* W_ix = (const float*)d_in[3];
    const float* b_ix = (const float*)d_in[4];
    const float* W_fx = (const float*)d_in[5];
    const float* b_fx = (const float*)d_in[6];
    const float* W_cx = (const float*)d_in[7];
    const float* b_cx = (const float*)d_in[8];
    const float* W_ox = (const float*)d_in[9];
    const float* b_ox = (const float*)d_in[10];
    const float* W_ih = (const float*)d_in[11];
    const float* b_ih = (const float*)d_in[12];
    const float* W_ic = (const float*)d_in[13];
    const float* b_ic = (const float*)d_in[14];
    const float* W_fh = (const float*)d_in[15];
    const float* b_fh = (const float*)d_in[16];
    const float* W_fc = (const float*)d_in[17];
    const float* b_fc = (const float*)d_in[18];
    const float* W_ch = (const float*)d_in[19];
    const float* b_ch = (const float*)d_in[20];
    const float* W_oh = (const float*)d_in[21];
    const float* b_oh = (const float*)d_in[22];
    const float* W_oc = (const float*)d_in[23];
    const float* b_oc = (const float*)d_in[24];
    float* out = (float*)d_out;

    cudaFuncSetAttribute(gemm_kernel, cudaFuncAttributeMaxDynamicSharedMemorySize, SMEM_DYN);

    pack_A1<<<2048, 256>>>(x, h, c);
    pack_W1<<<8192, 256>>>(W_ix, W_fx, W_cx, W_ox, W_ih, W_ic, W_fh, W_fc, W_ch, W_oh);
    pack_W2<<<1024, 256>>>(W_oc);

    dim3 g1(BB / BM, N1 / BN);   // 32 x 32
    gemm_kernel<<<g1, 256, SMEM_DYN>>>(0);

    ew1<<<4096, 256>>>(c, b_ix, b_ih, b_ic, b_fx, b_fh, b_fc, b_cx, b_ch, out);

    dim3 g2(BB / BM, HH / BN);   // 32 x 8
    gemm_kernel<<<g2, 256, SMEM_DYN>>>(1);

    ew2<<<4096, 256>>>(b_ox, b_oh, b_oc, out);
}

// round 9
// speedup vs baseline: 1.5752x; 1.4017x over previous
#include <cuda_runtime.h>
#include <cuda_fp16.h>
#include <cstdint>
#include <cstddef>
#include <math.h>

// ---------------- problem dims ----------------
#define BB 4096
#define HH 2048
#define K1 6144          // K for GEMM1: [x|h|c]
#define N1 8192          // N for GEMM1: 4 gates * 2048

// ---------------- GEMM tile config ----------------
#define BM 128
#define BN 256
#define BK 64            // fp16 elements per chunk (128B data per row)
#define ROWB 144         // smem row stride bytes (128 data + 16 pad)
#define A_TILE_BYTES (BM * ROWB)             // 18432
#define B_TILE_BYTES (BN * ROWB)             // 36864
#define ST_AH 0
#define ST_AL A_TILE_BYTES
#define ST_B  (2 * A_TILE_BYTES)
#define STAGE_BYTES (2 * A_TILE_BYTES + B_TILE_BYTES)       // 73728
#define NSTAGE 3
#define SMEM_DYN (NSTAGE * STAGE_BYTES + 128)               // 221312

// ---------------- device scratch (static; alloc APIs are forbidden) ------
__device__ __half g_A1hi[(size_t)BB * K1];
__device__ __half g_A1lo[(size_t)BB * K1];
__device__ __half g_W1[(size_t)N1 * K1];
__device__ __half g_W2[(size_t)HH * HH];
__device__ __half g_A2hi[(size_t)BB * HH];
__device__ __half g_A2lo[(size_t)BB * HH];
__device__ float  g_C[(size_t)BB * N1];

// ---------------- helpers ----------------
__device__ __forceinline__ uint32_t smem_u32(const void* p) {
    uint32_t a;
    asm("{ .reg .u64 t; cvta.to.shared.u64 t, %1; cvt.u32.u64 %0, t; }" : "=r"(a) : "l"(p));
    return a;
}

__device__ __forceinline__ void cp_async16(uint32_t dst, const void* src) {
    asm volatile("cp.async.cg.shared.global [%0], [%1], 16;" :: "r"(dst), "l"(src));
}

__device__ __forceinline__ void ldmatrix_x4(uint32_t* r, uint32_t addr) {
    asm volatile("ldmatrix.sync.aligned.m8n8.x4.shared.b16 {%0,%1,%2,%3}, [%4];"
        : "=r"(r[0]), "=r"(r[1]), "=r"(r[2]), "=r"(r[3]) : "r"(addr));
}

__device__ __forceinline__ uint32_t lds32(uint32_t addr) {
    uint32_t v;
    asm volatile("ld.shared.b32 %0, [%1];" : "=r"(v) : "r"(addr));
    return v;
}

__device__ __forceinline__ void mma_16816(float* c, const uint32_t* a, const uint32_t* b) {
    asm volatile(
        "mma.sync.aligned.m16n8k16.row.col.f32.f16.f16.f32 "
        "{%0,%1,%2,%3}, {%4,%5,%6,%7}, {%8,%9}, {%0,%1,%2,%3};"
        : "+f"(c[0]), "+f"(c[1]), "+f"(c[2]), "+f"(c[3])
        : "r"(a[0]), "r"(a[1]), "r"(a[2]), "r"(a[3]), "r"(b[0]), "r"(b[1]));
}

__device__ __forceinline__ void split_store(__half* hi, __half* lo, size_t i, float v) {
    __half h = __float2half_rn(v);
    hi[i] = h;
    lo[i] = __float2half_rn(v - __half2float(h));
}

// ---------------- packing kernels ----------------
__global__ void pack_A1(const float* __restrict__ x, const float* __restrict__ h,
                        const float* __restrict__ c) {
    size_t n = (size_t)BB * K1;
    for (size_t i = blockIdx.x * (size_t)blockDim.x + threadIdx.x; i < n;
         i += (size_t)gridDim.x * blockDim.x) {
        size_t m = i / K1;
        int k = (int)(i - m * K1);
        float v;
        if (k < HH)          v = x[m * HH + k];
        else if (k < 2 * HH) v = h[m * HH + (k - HH)];
        else                 v = c[m * HH + (k - 2 * HH)];
        split_store(g_A1hi, g_A1lo, i, v);
    }
}

__global__ void pack_W1(const float* __restrict__ Wix, const float* __restrict__ Wfx,
                        const float* __restrict__ Wcx, const float* __restrict__ Wox,
                        const float* __restrict__ Wih, const float* __restrict__ Wic,
                        const float* __restrict__ Wfh, const float* __restrict__ Wfc,
                        const float* __restrict__ Wch, const float* __restrict__ Woh) {
    size_t n = (size_t)N1 * K1;
    for (size_t i = blockIdx.x * (size_t)blockDim.x + threadIdx.x; i < n;
         i += (size_t)gridDim.x * blockDim.x) {
        size_t row = i / K1;
        int k = (int)(i - row * K1);
        int gate = (int)(row >> 11);
        int j = (int)(row & 2047);
        int seg = k >> 11;
        int kk = k & 2047;
        const float* W = nullptr;
        switch (gate * 3 + seg) {
            case 0:  W = Wix; break;
            case 1:  W = Wih; break;
            case 2:  W = Wic; break;
            case 3:  W = Wfx; break;
            case 4:  W = Wfh; break;
            case 5:  W = Wfc; break;
            case 6:  W = Wcx; break;
            case 7:  W = Wch; break;
            case 9:  W = Wox; break;
            case 10: W = Woh; break;
            default: break;   // gate g/o c-slot: zero (never read: variable-K skips it)
        }
        float v = W ? W[(size_t)j * HH + kk] : 0.0f;
        g_W1[i] = __float2half_rn(v);
    }
}

__global__ void pack_W2(const float* __restrict__ Woc) {
    size_t n = (size_t)HH * HH;
    for (size_t i = blockIdx.x * (size_t)blockDim.x + threadIdx.x; i < n;
         i += (size_t)gridDim.x * blockDim.x) {
        g_W2[i] = __float2half_rn(Woc[i]);
    }
}

// ---------------- GEMM: C = Ahi*B^T + Alo*B^T (fp16, fp32 accum) -----------
// cp.async 3-stage pipeline, BK=64, wait_group 1, one barrier per chunk.
// CTA tile 128x256, 8 warps as 2(M) x 4(N), warp tile 64x64.
__global__ void __launch_bounds__(256, 1)
gemm_kernel(int which) {
    const __half *Ahi, *Alo, *Bp;
    float* C;
    int K, Keff;
    const size_t brow0 = (size_t)blockIdx.y * BN;
    if (which == 0) {
        Ahi = g_A1hi; Alo = g_A1lo; Bp = g_W1;
        C = g_C; K = K1;
        Keff = (brow0 >= 4096) ? 4096 : 6144;   // gates g,o have zero c-slot
    } else {
        Ahi = g_A2hi; Alo = g_A2lo; Bp = g_W2;
        C = g_C + 2 * HH;   // gate-g column region (already consumed by ew1)
        K = HH; Keff = HH;
    }
    const int ldc = N1;
    const size_t arow0 = (size_t)blockIdx.x * BM;
    const int nchunk = Keff / BK;
    const int tid = threadIdx.x;
    const int lane = tid & 31;
    const int wid = tid >> 5;
    const int warpM = wid & 1;   // 2 warps over M: 64 rows each
    const int warpN = wid >> 1;  // 4 warps over N: 64 cols each

    extern __shared__ char dsmem[];
    const uint32_t sb = (smem_u32(dsmem) + 127u) & ~127u;

    // loader for chunk j into stage s (always commits, possibly empty group)
    auto load_chunk = [&](int j, int s) {
        if (j < nchunk) {
            const uint32_t stage = sb + s * STAGE_BYTES;
            const size_t kof = (size_t)j * BK;
            #pragma unroll
            for (int it = 0; it < 16; ++it) {
                int idx = tid + it * 256;        // 0..4095
                int g = idx & 7;                 // 16B segment within 128B row
                int rs = idx >> 3;               // 0..511: tile-row id
                const __half* src;
                uint32_t dstbase;
                int r;
                if (rs < 128)      { r = rs;       src = Ahi + (arow0 + r) * K + kof; dstbase = stage + ST_AH; }
                else if (rs < 256) { r = rs - 128; src = Alo + (arow0 + r) * K + kof; dstbase = stage + ST_AL; }
                else               { r = rs - 256; src = Bp  + (brow0 + r) * K + kof; dstbase = stage + ST_B;  }
                uint32_t dst = dstbase + (uint32_t)r * ROWB + (uint32_t)g * 16u;
                cp_async16(dst, (const void*)(src + g * 8));
            }
        }
        asm volatile("cp.async.commit_group;" ::: "memory");
    };

    float acc[4][8][4];
    #pragma unroll
    for (int mi = 0; mi < 4; ++mi)
        #pragma unroll
        for (int ni = 0; ni < 8; ++ni)
            #pragma unroll
            for (int q = 0; q < 4; ++q) acc[mi][ni][q] = 0.0f;

    load_chunk(0, 0);
    load_chunk(1, 1);

    for (int j = 0; j < nchunk; ++j) {
        const int s = j % NSTAGE;
        // chunk j ready (j+1 may still be in flight); recycle slot (j+2)%3.
        asm volatile("cp.async.wait_group 1;" ::: "memory");
        __syncthreads();          // all warps done with compute(j-1) -> its slot is free
        load_chunk(j + 2, (j + 2) % NSTAGE);

        const uint32_t stage = sb + s * STAGE_BYTES;
        const uint32_t a_hi = stage + ST_AH + (warpM * 64 + (lane & 15)) * ROWB + (lane >> 4) * 16;
        const uint32_t a_lo = stage + ST_AL + (warpM * 64 + (lane & 15)) * ROWB + (lane >> 4) * 16;
        const uint32_t b_0  = stage + ST_B  + (warpN * 64 + (lane >> 2)) * ROWB + (lane & 3) * 4;

        #pragma unroll
        for (int ks = 0; ks < 4; ++ks) {     // four k16 steps per BK=64 chunk
            const uint32_t koff = ks * 32;   // 16 fp16 = 32 bytes
            uint32_t ah[4][4], al[4][4];
            #pragma unroll
            for (int mi = 0; mi < 4; ++mi) {
                ldmatrix_x4(ah[mi], a_hi + mi * 16 * ROWB + koff);
                ldmatrix_x4(al[mi], a_lo + mi * 16 * ROWB + koff);
            }
            #pragma unroll
            for (int np = 0; np < 4; ++np) {
                const int ni0 = np * 2, ni1 = np * 2 + 1;
                uint32_t b0[2], b1[2];
                const uint32_t bro0 = ni0 * 8 * ROWB + koff;
                const uint32_t bro1 = ni1 * 8 * ROWB + koff;
                b0[0] = lds32(b_0 + bro0);      b0[1] = lds32(b_0 + bro0 + 16);
                b1[0] = lds32(b_0 + bro1);      b1[1] = lds32(b_0 + bro1 + 16);
                // pass 1: Ahi * B
                #pragma unroll
                for (int mi = 0; mi < 4; ++mi) mma_16816(acc[mi][ni0], ah[mi], b0);
                #pragma unroll
                for (int mi = 0; mi < 4; ++mi) mma_16816(acc[mi][ni1], ah[mi], b1);
                // pass 2: Alo * B
                #pragma unroll
                for (int mi = 0; mi < 4; ++mi) mma_16816(acc[mi][ni0], al[mi], b0);
                #pragma unroll
                for (int mi = 0; mi < 4; ++mi) mma_16816(acc[mi][ni1], al[mi], b1);
            }
        }
    }

    // epilogue: fp32 store
    #pragma unroll
    for (int mi = 0; mi < 4; ++mi) {
        const size_t m0 = arow0 + warpM * 64 + mi * 16 + (lane >> 2);
        #pragma unroll
        for (int ni = 0; ni < 8; ++ni) {
            const size_t n0 = brow0 + warpN * 64 + ni * 8 + (lane & 3) * 2;
            float2 v0 = make_float2(acc[mi][ni][0], acc[mi][ni][1]);
            float2 v1 = make_float2(acc[mi][ni][2], acc[mi][ni][3]);
            *reinterpret_cast<float2*>(C + m0 * ldc + n0)       = v0;
            *reinterpret_cast<float2*>(C + (m0 + 8) * ldc + n0) = v1;
        }
    }
}

// ---------------- elementwise 1: gates i,f,g -> c_next; pack A2 -------------
__global__ void ew1(const float* __restrict__ c,
                    const float* __restrict__ b_ix, const float* __restrict__ b_ih,
                    const float* __restrict__ b_ic,
                    const float* __restrict__ b_fx, const float* __restrict__ b_fh,
                    const float* __restrict__ b_fc,
                    const float* __restrict__ b_cx, const float* __restrict__ b_ch,
                    float* __restrict__ out) {
    const size_t n = (size_t)BB * HH;
    for (size_t i = blockIdx.x * (size_t)blockDim.x + threadIdx.x; i < n;
         i += (size_t)gridDim.x * blockDim.x) {
        size_t m = i / HH;
        int j = (int)(i - m * HH);
        const float* crow = g_C + m * (size_t)N1;
        float ip = crow[j]        + b_ix[j] + b_ih[j] + b_ic[j];
        float fp = crow[2048 + j] + b_fx[j] + b_fh[j] + b_fc[j];
        float gp = crow[4096 + j] + b_cx[j] + b_ch[j];
        float ii = 1.0f / (1.0f + expf(-ip));
        float ff = 1.0f / (1.0f + expf(-fp));
        float gg = tanhf(gp);
        float cn = ff * c[i] + ii * gg;
        out[2 * n + i] = cn;                       // c_next
        split_store(g_A2hi, g_A2lo, i, cn);        // A2 for GEMM2
    }
}

// ---------------- elementwise 2: o gate, h_next ----------------
__global__ void ew2(const float* __restrict__ b_ox, const float* __restrict__ b_oh,
                    const float* __restrict__ b_oc,
                    float* __restrict__ out) {
    const size_t n = (size_t)BB * HH;
    for (size_t i = blockIdx.x * (size_t)blockDim.x + threadIdx.x; i < n;
         i += (size_t)gridDim.x * blockDim.x) {
        size_t m = i / HH;
        int j = (int)(i - m * HH);
        const float* crow = g_C + m * (size_t)N1;
        float op = crow[6144 + j] + crow[4096 + j] + b_ox[j] + b_oh[j] + b_oc[j];
        float cn = out[2 * n + i];
        float t = tanhf(cn);
        float o = (1.0f / (1.0f + expf(-op))) * t;
        out[i] = o;           // o
        out[n + i] = o * t;   // h_next
    }
}

// ---------------- launch ----------------
extern "C" void kernel_launch(void* const* d_in, const int* in_sizes, int n_in,
                              void* d_out, int out_size) {
    const float* x    = (const float*)d_in[0];
    const float* h    = (const float*)d_in[1];
    const float* c    = (const float*)d_in[2];
    const float* W_ix = (const float*)d_in[3];
    const float* b_ix = (const float*)d_in[4];
    const float* W_fx = (const float*)d_in[5];
    const float* b_fx = (const float*)d_in[6];
    const float* W_cx = (const float*)d_in[7];
    const float* b_cx = (const float*)d_in[8];
    const float* W_ox = (const float*)d_in[9];
    const float* b_ox = (const float*)d_in[10];
    const float* W_ih = (const float*)d_in[11];
    const float* b_ih = (const float*)d_in[12];
    const float* W_ic = (const float*)d_in[13];
    const float* b_ic = (const float*)d_in[14];
    const float* W_fh = (const float*)d_in[15];
    const float* b_fh = (const float*)d_in[16];
    const float* W_fc = (const float*)d_in[17];
    const float* b_fc = (const float*)d_in[18];
    const float* W_ch = (const float*)d_in[19];
    const float* b_ch = (const float*)d_in[20];
    const float* W_oh = (const float*)d_in[21];
    const float* b_oh = (const float*)d_in[22];
    const float* W_oc = (const float*)d_in[23];
    const float* b_oc = (const float*)d_in[24];
    float* out = (float*)d_out;

    cudaFuncSetAttribute(gemm_kernel, cudaFuncAttributeMaxDynamicSharedMemorySize, SMEM_DYN);

    pack_A1<<<2048, 256>>>(x, h, c);
    pack_W1<<<8192, 256>>>(W_ix, W_fx, W_cx, W_ox, W_ih, W_ic, W_fh, W_fc, W_ch, W_oh);
    pack_W2<<<1024, 256>>>(W_oc);

    dim3 g1(BB / BM, N1 / BN);   // 32 x 32
    gemm_kernel<<<g1, 256, SMEM_DYN>>>(0);

    ew1<<<4096, 256>>>(c, b_ix, b_ih, b_ic, b_fx, b_fh, b_fc, b_cx, b_ch, out);

    dim3 g2(BB / BM, HH / BN);   // 32 x 8
    gemm_kernel<<<g2, 256, SMEM_DYN>>>(1);

    ew2<<<4096, 256>>>(b_ox, b_oh, b_oc, out);
}

// round 10
// speedup vs baseline: 1.6531x; 1.0494x over previous
#include <cuda_runtime.h>
#include <cuda_fp16.h>
#include <cstdint>
#include <cstddef>
#include <math.h>

// ---------------- problem dims ----------------
#define BB 4096
#define HH 2048
#define K1 6144          // K for GEMM1: [x|h|c]
#define N1 8192          // N for GEMM1: 4 gates * 2048

// ---------------- GEMM tile config ----------------
#define BM 128
#define BN 256
#define BK 64            // fp16 elements per chunk (128B data per row)
#define ROWB 144         // smem row stride bytes (128 data + 16 pad)
#define A_TILE_BYTES (BM * ROWB)             // 18432
#define B_TILE_BYTES (BN * ROWB)             // 36864
#define ST_A 0
#define ST_B A_TILE_BYTES
#define STAGE_BYTES (A_TILE_BYTES + B_TILE_BYTES)           // 55296
#define NSTAGE 4
#define SMEM_DYN (NSTAGE * STAGE_BYTES + 128)               // 221312

// ---------------- device scratch (static; alloc APIs are forbidden) ------
__device__ __half g_A1[(size_t)BB * K1];
__device__ __half g_W1[(size_t)N1 * K1];
__device__ __half g_W2[(size_t)HH * HH];
__device__ __half g_A2[(size_t)BB * HH];
__device__ float  g_C[(size_t)BB * N1];

// ---------------- helpers ----------------
__device__ __forceinline__ uint32_t smem_u32(const void* p) {
    uint32_t a;
    asm("{ .reg .u64 t; cvta.to.shared.u64 t, %1; cvt.u32.u64 %0, t; }" : "=r"(a) : "l"(p));
    return a;
}

__device__ __forceinline__ void cp_async16(uint32_t dst, const void* src) {
    asm volatile("cp.async.cg.shared.global [%0], [%1], 16;" :: "r"(dst), "l"(src));
}

__device__ __forceinline__ void ldmatrix_x4(uint32_t* r, uint32_t addr) {
    asm volatile("ldmatrix.sync.aligned.m8n8.x4.shared.b16 {%0,%1,%2,%3}, [%4];"
        : "=r"(r[0]), "=r"(r[1]), "=r"(r[2]), "=r"(r[3]) : "r"(addr));
}

__device__ __forceinline__ uint32_t lds32(uint32_t addr) {
    uint32_t v;
    asm volatile("ld.shared.b32 %0, [%1];" : "=r"(v) : "r"(addr));
    return v;
}

__device__ __forceinline__ void mma_16816(float* c, const uint32_t* a, const uint32_t* b) {
    asm volatile(
        "mma.sync.aligned.m16n8k16.row.col.f32.f16.f16.f32 "
        "{%0,%1,%2,%3}, {%4,%5,%6,%7}, {%8,%9}, {%0,%1,%2,%3};"
        : "+f"(c[0]), "+f"(c[1]), "+f"(c[2]), "+f"(c[3])
        : "r"(a[0]), "r"(a[1]), "r"(a[2]), "r"(a[3]), "r"(b[0]), "r"(b[1]));
}

// ---------------- packing kernels ----------------
__global__ void pack_A1(const float* __restrict__ x, const float* __restrict__ h,
                        const float* __restrict__ c) {
    size_t n = (size_t)BB * K1;
    for (size_t i = blockIdx.x * (size_t)blockDim.x + threadIdx.x; i < n;
         i += (size_t)gridDim.x * blockDim.x) {
        size_t m = i / K1;
        int k = (int)(i - m * K1);
        float v;
        if (k < HH)          v = x[m * HH + k];
        else if (k < 2 * HH) v = h[m * HH + (k - HH)];
        else                 v = c[m * HH + (k - 2 * HH)];
        g_A1[i] = __float2half_rn(v);
    }
}

__global__ void pack_W1(const float* __restrict__ Wix, const float* __restrict__ Wfx,
                        const float* __restrict__ Wcx, const float* __restrict__ Wox,
                        const float* __restrict__ Wih, const float* __restrict__ Wic,
                        const float* __restrict__ Wfh, const float* __restrict__ Wfc,
                        const float* __restrict__ Wch, const float* __restrict__ Woh) {
    size_t n = (size_t)N1 * K1;
    for (size_t i = blockIdx.x * (size_t)blockDim.x + threadIdx.x; i < n;
         i += (size_t)gridDim.x * blockDim.x) {
        size_t row = i / K1;
        int k = (int)(i - row * K1);
        int gate = (int)(row >> 11);
        int j = (int)(row & 2047);
        int seg = k >> 11;
        int kk = k & 2047;
        const float* W = nullptr;
        switch (gate * 3 + seg) {
            case 0:  W = Wix; break;
            case 1:  W = Wih; break;
            case 2:  W = Wic; break;
            case 3:  W = Wfx; break;
            case 4:  W = Wfh; break;
            case 5:  W = Wfc; break;
            case 6:  W = Wcx; break;
            case 7:  W = Wch; break;
            case 9:  W = Wox; break;
            case 10: W = Woh; break;
            default: break;   // gate g/o c-slot: zero (never read: variable-K skips it)
        }
        float v = W ? W[(size_t)j * HH + kk] : 0.0f;
        g_W1[i] = __float2half_rn(v);
    }
}

__global__ void pack_W2(const float* __restrict__ Woc) {
    size_t n = (size_t)HH * HH;
    for (size_t i = blockIdx.x * (size_t)blockDim.x + threadIdx.x; i < n;
         i += (size_t)gridDim.x * blockDim.x) {
        g_W2[i] = __float2half_rn(Woc[i]);
    }
}

// ---------------- GEMM: C = A*B^T (fp16 operands, fp32 accumulate) ----------
// cp.async 4-stage pipeline, BK=64, wait_group 2, one barrier per chunk.
// CTA tile 128x256, 8 warps as 2(M) x 4(N), warp tile 64x64.
__global__ void __launch_bounds__(256, 1)
gemm_kernel(int which) {
    const __half *Ap, *Bp;
    float* C;
    int K, Keff;
    const size_t brow0 = (size_t)blockIdx.y * BN;
    if (which == 0) {
        Ap = g_A1; Bp = g_W1;
        C = g_C; K = K1;
        Keff = (brow0 >= 4096) ? 4096 : 6144;   // gates g,o have zero c-slot
    } else {
        Ap = g_A2; Bp = g_W2;
        C = g_C + 2 * HH;   // gate-g column region (already consumed by ew1)
        K = HH; Keff = HH;
    }
    const int ldc = N1;
    const size_t arow0 = (size_t)blockIdx.x * BM;
    const int nchunk = Keff / BK;
    const int tid = threadIdx.x;
    const int lane = tid & 31;
    const int wid = tid >> 5;
    const int warpM = wid & 1;   // 2 warps over M: 64 rows each
    const int warpN = wid >> 1;  // 4 warps over N: 64 cols each

    extern __shared__ char dsmem[];
    const uint32_t sb = (smem_u32(dsmem) + 127u) & ~127u;

    // loader for chunk j into stage s (always commits, possibly empty group)
    auto load_chunk = [&](int j, int s) {
        if (j < nchunk) {
            const uint32_t stage = sb + s * STAGE_BYTES;
            const size_t kof = (size_t)j * BK;
            #pragma unroll
            for (int it = 0; it < 12; ++it) {
                int idx = tid + it * 256;        // 0..3071
                int g = idx & 7;                 // 16B segment within 128B row
                int rs = idx >> 3;               // 0..383: tile-row id
                const __half* src;
                uint32_t dstbase;
                int r;
                if (rs < 128) { r = rs;       src = Ap + (arow0 + r) * K + kof; dstbase = stage + ST_A; }
                else          { r = rs - 128; src = Bp + (brow0 + r) * K + kof; dstbase = stage + ST_B; }
                uint32_t dst = dstbase + (uint32_t)r * ROWB + (uint32_t)g * 16u;
                cp_async16(dst, (const void*)(src + g * 8));
            }
        }
        asm volatile("cp.async.commit_group;" ::: "memory");
    };

    float acc[4][8][4];
    #pragma unroll
    for (int mi = 0; mi < 4; ++mi)
        #pragma unroll
        for (int ni = 0; ni < 8; ++ni)
            #pragma unroll
            for (int q = 0; q < 4; ++q) acc[mi][ni][q] = 0.0f;

    load_chunk(0, 0);
    load_chunk(1, 1);
    load_chunk(2, 2);

    for (int j = 0; j < nchunk; ++j) {
        const int s = j % NSTAGE;
        // chunk j ready (j+1, j+2 may be in flight); recycle slot (j+3)%4.
        asm volatile("cp.async.wait_group 2;" ::: "memory");
        __syncthreads();          // all warps done with compute(j-1) -> slot (j+3)%4 free
        load_chunk(j + 3, (j + 3) % NSTAGE);

        const uint32_t stage = sb + s * STAGE_BYTES;
        const uint32_t a_0 = stage + ST_A + (warpM * 64 + (lane & 15)) * ROWB + (lane >> 4) * 16;
        const uint32_t b_0 = stage + ST_B + (warpN * 64 + (lane >> 2)) * ROWB + (lane & 3) * 4;

        #pragma unroll
        for (int ks = 0; ks < 4; ++ks) {     // four k16 steps per BK=64 chunk
            const uint32_t koff = ks * 32;   // 16 fp16 = 32 bytes
            uint32_t a[4][4];
            #pragma unroll
            for (int mi = 0; mi < 4; ++mi)
                ldmatrix_x4(a[mi], a_0 + mi * 16 * ROWB + koff);
            #pragma unroll
            for (int np = 0; np < 4; ++np) {
                const int ni0 = np * 2, ni1 = np * 2 + 1;
                uint32_t b0[2], b1[2];
                const uint32_t bro0 = ni0 * 8 * ROWB + koff;
                const uint32_t bro1 = ni1 * 8 * ROWB + koff;
                b0[0] = lds32(b_0 + bro0);      b0[1] = lds32(b_0 + bro0 + 16);
                b1[0] = lds32(b_0 + bro1);      b1[1] = lds32(b_0 + bro1 + 16);
                #pragma unroll
                for (int mi = 0; mi < 4; ++mi) mma_16816(acc[mi][ni0], a[mi], b0);
                #pragma unroll
                for (int mi = 0; mi < 4; ++mi) mma_16816(acc[mi][ni1], a[mi], b1);
            }
        }
    }

    // epilogue: fp32 store
    #pragma unroll
    for (int mi = 0; mi < 4; ++mi) {
        const size_t m0 = arow0 + warpM * 64 + mi * 16 + (lane >> 2);
        #pragma unroll
        for (int ni = 0; ni < 8; ++ni) {
            const size_t n0 = brow0 + warpN * 64 + ni * 8 + (lane & 3) * 2;
            float2 v0 = make_float2(acc[mi][ni][0], acc[mi][ni][1]);
            float2 v1 = make_float2(acc[mi][ni][2], acc[mi][ni][3]);
            *reinterpret_cast<float2*>(C + m0 * ldc + n0)       = v0;
            *reinterpret_cast<float2*>(C + (m0 + 8) * ldc + n0) = v1;
        }
    }
}

// ---------------- elementwise 1: gates i,f,g -> c_next; pack A2 -------------
__global__ void ew1(const float* __restrict__ c,
                    const float* __restrict__ b_ix, const float* __restrict__ b_ih,
                    const float* __restrict__ b_ic,
                    const float* __restrict__ b_fx, const float* __restrict__ b_fh,
                    const float* __restrict__ b_fc,
                    const float* __restrict__ b_cx, const float* __restrict__ b_ch,
                    float* __restrict__ out) {
    const size_t n = (size_t)BB * HH;
    for (size_t i = blockIdx.x * (size_t)blockDim.x + threadIdx.x; i < n;
         i += (size_t)gridDim.x * blockDim.x) {
        size_t m = i / HH;
        int j = (int)(i - m * HH);
        const float* crow = g_C + m * (size_t)N1;
        float ip = crow[j]        + b_ix[j] + b_ih[j] + b_ic[j];
        float fp = crow[2048 + j] + b_fx[j] + b_fh[j] + b_fc[j];
        float gp = crow[4096 + j] + b_cx[j] + b_ch[j];
        float ii = 1.0f / (1.0f + expf(-ip));
        float ff = 1.0f / (1.0f + expf(-fp));
        float gg = tanhf(gp);
        float cn = ff * c[i] + ii * gg;
        out[2 * n + i] = cn;                       // c_next
        g_A2[i] = __float2half_rn(cn);             // A2 for GEMM2
    }
}

// ---------------- elementwise 2: o gate, h_next ----------------
__global__ void ew2(const float* __restrict__ b_ox, const float* __restrict__ b_oh,
                    const float* __restrict__ b_oc,
                    float* __restrict__ out) {
    const size_t n = (size_t)BB * HH;
    for (size_t i = blockIdx.x * (size_t)blockDim.x + threadIdx.x; i < n;
         i += (size_t)gridDim.x * blockDim.x) {
        size_t m = i / HH;
        int j = (int)(i - m * HH);
        const float* crow = g_C + m * (size_t)N1;
        float op = crow[6144 + j] + crow[4096 + j] + b_ox[j] + b_oh[j] + b_oc[j];
        float cn = out[2 * n + i];
        float t = tanhf(cn);
        float o = (1.0f / (1.0f + expf(-op))) * t;
        out[i] = o;           // o
        out[n + i] = o * t;   // h_next
    }
}

// ---------------- launch ----------------
extern "C" void kernel_launch(void* const* d_in, const int* in_sizes, int n_in,
                              void* d_out, int out_size) {
    const float* x    = (const float*)d_in[0];
    const float* h    = (const float*)d_in[1];
    const float* c    = (const float*)d_in[2];
    const float* W_ix = (const float*)d_in[3];
    const float* b_ix = (const float*)d_in[4];
    const float* W_fx = (const float*)d_in[5];
    const float* b_fx = (const float*)d_in[6];
    const float* W_cx = (const float*)d_in[7];
    const float* b_cx = (const float*)d_in[8];
    const float* W_ox = (const float*)d_in[9];
    const float* b_ox = (const float*)d_in[10];
    const float* W_ih = (const float*)d_in[11];
    const float* b_ih = (const float*)d_in[12];
    const float* W_ic = (const float*)d_in[13];
    const float* b_ic = (const float*)d_in[14];
    const float* W_fh = (const float*)d_in[15];
    const float* b_fh = (const float*)d_in[16];
    const float* W_fc = (const float*)d_in[17];
    const float* b_fc = (const float*)d_in[18];
    const float* W_ch = (const float*)d_in[19];
    const float* b_ch = (const float*)d_in[20];
    const float* W_oh = (const float*)d_in[21];
    const float* b_oh = (const float*)d_in[22];
    const float* W_oc = (const float*)d_in[23];
    const float* b_oc = (const float*)d_in[24];
    float* out = (float*)d_out;

    cudaFuncSetAttribute(gemm_kernel, cudaFuncAttributeMaxDynamicSharedMemorySize, SMEM_DYN);

    pack_A1<<<2048, 256>>>(x, h, c);
    pack_W1<<<8192, 256>>>(W_ix, W_fx, W_cx, W_ox, W_ih, W_ic, W_fh, W_fc, W_ch, W_oh);
    pack_W2<<<1024, 256>>>(W_oc);

    dim3 g1(BB / BM, N1 / BN);   // 32 x 32
    gemm_kernel<<<g1, 256, SMEM_DYN>>>(0);

    ew1<<<4096, 256>>>(c, b_ix, b_ih, b_ic, b_fx, b_fh, b_fc, b_cx, b_ch, out);

    dim3 g2(BB / BM, HH / BN);   // 32 x 8
    gemm_kernel<<<g2, 256, SMEM_DYN>>>(1);

    ew2<<<4096, 256>>>(b_ox, b_oh, b_oc, out);
}

// round 12
// speedup vs baseline: 2.6031x; 1.5747x over previous
#include <cuda_runtime.h>
#include <cuda_fp16.h>
#include <cstdint>
#include <cstddef>
#include <math.h>

// ---------------- problem dims ----------------
#define BB 4096
#define HH 2048
#define K1 6144          // K for GEMM1: [x|h|c]
#define N1 8192          // N for GEMM1: 4 gates * 2048

// ---------------- GEMM tile config ----------------
#define BM 128
#define BN 128
#define BK 64            // fp16 elements per chunk (128B data per row)
#define ROWB 144         // smem row stride bytes (128 data + 16 pad)
#define A_TILE_BYTES (BM * ROWB)             // 18432
#define B_TILE_BYTES (BN * ROWB)             // 18432
#define ST_A 0
#define ST_B A_TILE_BYTES
#define STAGE_BYTES (A_TILE_BYTES + B_TILE_BYTES)           // 36864
#define NSTAGE 3
#define SMEM_DYN (NSTAGE * STAGE_BYTES + 128)               // 110720

// ---------------- device scratch (static; alloc APIs are forbidden) ------
__device__ __half g_A1[(size_t)BB * K1];
__device__ __half g_W1[(size_t)N1 * K1];
__device__ __half g_W2[(size_t)HH * HH];
__device__ __half g_A2[(size_t)BB * HH];
__device__ float  g_C[(size_t)BB * N1];

// ---------------- helpers ----------------
__device__ __forceinline__ uint32_t smem_u32(const void* p) {
    uint32_t a;
    asm("{ .reg .u64 t; cvta.to.shared.u64 t, %1; cvt.u32.u64 %0, t; }" : "=r"(a) : "l"(p));
    return a;
}

__device__ __forceinline__ void cp_async16(uint32_t dst, const void* src) {
    asm volatile("cp.async.cg.shared.global [%0], [%1], 16;" :: "r"(dst), "l"(src));
}

__device__ __forceinline__ void ldmatrix_x4(uint32_t* r, uint32_t addr) {
    asm volatile("ldmatrix.sync.aligned.m8n8.x4.shared.b16 {%0,%1,%2,%3}, [%4];"
        : "=r"(r[0]), "=r"(r[1]), "=r"(r[2]), "=r"(r[3]) : "r"(addr));
}

__device__ __forceinline__ uint32_t lds32(uint32_t addr) {
    uint32_t v;
    asm volatile("ld.shared.b32 %0, [%1];" : "=r"(v) : "r"(addr));
    return v;
}

__device__ __forceinline__ void mma_16816(float* c, const uint32_t* a, const uint32_t* b) {
    asm volatile(
        "mma.sync.aligned.m16n8k16.row.col.f32.f16.f16.f32 "
        "{%0,%1,%2,%3}, {%4,%5,%6,%7}, {%8,%9}, {%0,%1,%2,%3};"
        : "+f"(c[0]), "+f"(c[1]), "+f"(c[2]), "+f"(c[3])
        : "r"(a[0]), "r"(a[1]), "r"(a[2]), "r"(a[3]), "r"(b[0]), "r"(b[1]));
}

// ---------------- packing kernels ----------------
__global__ void pack_A1(const float* __restrict__ x, const float* __restrict__ h,
                        const float* __restrict__ c) {
    size_t n = (size_t)BB * K1;
    for (size_t i = blockIdx.x * (size_t)blockDim.x + threadIdx.x; i < n;
         i += (size_t)gridDim.x * blockDim.x) {
        size_t m = i / K1;
        int k = (int)(i - m * K1);
        float v;
        if (k < HH)          v = x[m * HH + k];
        else if (k < 2 * HH) v = h[m * HH + (k - HH)];
        else                 v = c[m * HH + (k - 2 * HH)];
        g_A1[i] = __float2half_rn(v);
    }
}

__global__ void pack_W1(const float* __restrict__ Wix, const float* __restrict__ Wfx,
                        const float* __restrict__ Wcx, const float* __restrict__ Wox,
                        const float* __restrict__ Wih, const float* __restrict__ Wic,
                        const float* __restrict__ Wfh, const float* __restrict__ Wfc,
                        const float* __restrict__ Wch, const float* __restrict__ Woh) {
    size_t n = (size_t)N1 * K1;
    for (size_t i = blockIdx.x * (size_t)blockDim.x + threadIdx.x; i < n;
         i += (size_t)gridDim.x * blockDim.x) {
        size_t row = i / K1;
        int k = (int)(i - row * K1);
        int gate = (int)(row >> 11);
        int j = (int)(row & 2047);
        int seg = k >> 11;
        int kk = k & 2047;
        const float* W = nullptr;
        switch (gate * 3 + seg) {
            case 0:  W = Wix; break;
            case 1:  W = Wih; break;
            case 2:  W = Wic; break;
            case 3:  W = Wfx; break;
            case 4:  W = Wfh; break;
            case 5:  W = Wfc; break;
            case 6:  W = Wcx; break;
            case 7:  W = Wch; break;
            case 9:  W = Wox; break;
            case 10: W = Woh; break;
            default: break;   // gate g/o c-slot: zero (never read: variable-K skips it)
        }
        float v = W ? W[(size_t)j * HH + kk] : 0.0f;
        g_W1[i] = __float2half_rn(v);
    }
}

__global__ void pack_W2(const float* __restrict__ Woc) {
    size_t n = (size_t)HH * HH;
    for (size_t i = blockIdx.x * (size_t)blockDim.x + threadIdx.x; i < n;
         i += (size_t)gridDim.x * blockDim.x) {
        g_W2[i] = __float2half_rn(Woc[i]);
    }
}

// ---------------- GEMM: C = A*B^T (fp16 operands, fp32 accumulate) ----------
// cp.async 3-stage pipeline, BK=64, wait_group 1, one barrier per chunk.
// CTA tile 128x128, 8 warps as 2(M) x 4(N), warp tile 64x32, 2 CTAs/SM.
__global__ void __launch_bounds__(256, 2)
gemm_kernel(int which) {
    const __half *Ap, *Bp;
    float* C;
    int K, Keff;
    const size_t brow0 = (size_t)blockIdx.y * BN;
    if (which == 0) {
        Ap = g_A1; Bp = g_W1;
        C = g_C; K = K1;
        Keff = (brow0 >= 4096) ? 4096 : 6144;   // gates g,o have zero c-slot
    } else {
        Ap = g_A2; Bp = g_W2;
        C = g_C + 2 * HH;   // gate-g column region (already consumed by ew1)
        K = HH; Keff = HH;
    }
    const int ldc = N1;
    const size_t arow0 = (size_t)blockIdx.x * BM;
    const int nchunk = Keff / BK;
    const int tid = threadIdx.x;
    const int lane = tid & 31;
    const int wid = tid >> 5;
    const int warpM = wid & 1;   // 2 warps over M: 64 rows each
    const int warpN = wid >> 1;  // 4 warps over N: 32 cols each

    extern __shared__ char dsmem[];
    const uint32_t sb = (smem_u32(dsmem) + 127u) & ~127u;

    // loader for chunk j into stage s (always commits, possibly empty group)
    auto load_chunk = [&](int j, int s) {
        if (j < nchunk) {
            const uint32_t stage = sb + s * STAGE_BYTES;
            const size_t kof = (size_t)j * BK;
            #pragma unroll
            for (int it = 0; it < 8; ++it) {
                int idx = tid + it * 256;        // 0..2047
                int g = idx & 7;                 // 16B segment within 128B row
                int rs = idx >> 3;               // 0..255: tile-row id
                const __half* src;
                uint32_t dstbase;
                int r;
                if (rs < 128) { r = rs;       src = Ap + (arow0 + r) * K + kof; dstbase = stage + ST_A; }
                else          { r = rs - 128; src = Bp + (brow0 + r) * K + kof; dstbase = stage + ST_B; }
                uint32_t dst = dstbase + (uint32_t)r * ROWB + (uint32_t)g * 16u;
                cp_async16(dst, (const void*)(src + g * 8));
            }
        }
        asm volatile("cp.async.commit_group;" ::: "memory");
    };

    float acc[4][4][4];
    #pragma unroll
    for (int mi = 0; mi < 4; ++mi)
        #pragma unroll
        for (int ni = 0; ni < 4; ++ni)
            #pragma unroll
            for (int q = 0; q < 4; ++q) acc[mi][ni][q] = 0.0f;

    load_chunk(0, 0);
    load_chunk(1, 1);

    for (int j = 0; j < nchunk; ++j) {
        const int s = j % NSTAGE;
        // chunk j ready (j+1 may be in flight); recycle slot (j+2)%3.
        asm volatile("cp.async.wait_group 1;" ::: "memory");
        __syncthreads();          // all warps done with compute(j-1) -> slot (j+2)%3 free
        load_chunk(j + 2, (j + 2) % NSTAGE);

        const uint32_t stage = sb + s * STAGE_BYTES;
        const uint32_t a_0 = stage + ST_A + (warpM * 64 + (lane & 15)) * ROWB + (lane >> 4) * 16;
        const uint32_t b_0 = stage + ST_B + (warpN * 32 + (lane >> 2)) * ROWB + (lane & 3) * 4;

        #pragma unroll
        for (int ks = 0; ks < 4; ++ks) {     // four k16 steps per BK=64 chunk
            const uint32_t koff = ks * 32;   // 16 fp16 = 32 bytes
            uint32_t a[4][4];
            #pragma unroll
            for (int mi = 0; mi < 4; ++mi)
                ldmatrix_x4(a[mi], a_0 + mi * 16 * ROWB + koff);
            #pragma unroll
            for (int np = 0; np < 2; ++np) {
                const int ni0 = np * 2, ni1 = np * 2 + 1;
                uint32_t b0[2], b1[2];
                const uint32_t bro0 = ni0 * 8 * ROWB + koff;
                const uint32_t bro1 = ni1 * 8 * ROWB + koff;
                b0[0] = lds32(b_0 + bro0);      b0[1] = lds32(b_0 + bro0 + 16);
                b1[0] = lds32(b_0 + bro1);      b1[1] = lds32(b_0 + bro1 + 16);
                #pragma unroll
                for (int mi = 0; mi < 4; ++mi) mma_16816(acc[mi][ni0], a[mi], b0);
                #pragma unroll
                for (int mi = 0; mi < 4; ++mi) mma_16816(acc[mi][ni1], a[mi], b1);
            }
        }
    }

    // epilogue: fp32 store
    #pragma unroll
    for (int mi = 0; mi < 4; ++mi) {
        const size_t m0 = arow0 + warpM * 64 + mi * 16 + (lane >> 2);
        #pragma unroll
        for (int ni = 0; ni < 4; ++ni) {
            const size_t n0 = brow0 + warpN * 32 + ni * 8 + (lane & 3) * 2;
            float2 v0 = make_float2(acc[mi][ni][0], acc[mi][ni][1]);
            float2 v1 = make_float2(acc[mi][ni][2], acc[mi][ni][3]);
            *reinterpret_cast<float2*>(C + m0 * ldc + n0)       = v0;
            *reinterpret_cast<float2*>(C + (m0 + 8) * ldc + n0) = v1;
        }
    }
}

// ---------------- elementwise 1: gates i,f,g -> c_next; pack A2 -------------
__global__ void ew1(const float* __restrict__ c,
                    const float* __restrict__ b_ix, const float* __restrict__ b_ih,
                    const float* __restrict__ b_ic,
                    const float* __restrict__ b_fx, const float* __restrict__ b_fh,
                    const float* __restrict__ b_fc,
                    const float* __restrict__ b_cx, const float* __restrict__ b_ch,
                    float* __restrict__ out) {
    const size_t n = (size_t)BB * HH;
    for (size_t i = blockIdx.x * (size_t)blockDim.x + threadIdx.x; i < n;
         i += (size_t)gridDim.x * blockDim.x) {
        size_t m = i / HH;
        int j = (int)(i - m * HH);
        const float* crow = g_C + m * (size_t)N1;
        float ip = crow[j]        + b_ix[j] + b_ih[j] + b_ic[j];
        float fp = crow[2048 + j] + b_fx[j] + b_fh[j] + b_fc[j];
        float gp = crow[4096 + j] + b_cx[j] + b_ch[j];
        float ii = 1.0f / (1.0f + expf(-ip));
        float ff = 1.0f / (1.0f + expf(-fp));
        float gg = tanhf(gp);
        float cn = ff * c[i] + ii * gg;
        out[2 * n + i] = cn;                       // c_next
        g_A2[i] = __float2half_rn(cn);             // A2 for GEMM2
    }
}

// ---------------- elementwise 2: o gate, h_next ----------------
__global__ void ew2(const float* __restrict__ b_ox, const float* __restrict__ b_oh,
                    const float* __restrict__ b_oc,
                    float* __restrict__ out) {
    const size_t n = (size_t)BB * HH;
    for (size_t i = blockIdx.x * (size_t)blockDim.x + threadIdx.x; i < n;
         i += (size_t)gridDim.x * blockDim.x) {
        size_t m = i / HH;
        int j = (int)(i - m * HH);
        const float* crow = g_C + m * (size_t)N1;
        float op = crow[6144 + j] + crow[4096 + j] + b_ox[j] + b_oh[j] + b_oc[j];
        float cn = out[2 * n + i];
        float t = tanhf(cn);
        float o = (1.0f / (1.0f + expf(-op))) * t;
        out[i] = o;           // o
        out[n + i] = o * t;   // h_next
    }
}

// ---------------- launch ----------------
extern "C" void kernel_launch(void* const* d_in, const int* in_sizes, int n_in,
                              void* d_out, int out_size) {
    const float* x    = (const float*)d_in[0];
    const float* h    = (const float*)d_in[1];
    const float* c    = (const float*)d_in[2];
    const float* W_ix = (const float*)d_in[3];
    const float* b_ix = (const float*)d_in[4];
    const float* W_fx = (const float*)d_in[5];
    const float* b_fx = (const float*)d_in[6];
    const float* W_cx = (const float*)d_in[7];
    const float* b_cx = (const float*)d_in[8];
    const float* W_ox = (const float*)d_in[9];
    const float* b_ox = (const float*)d_in[10];
    const float* W_ih = (const float*)d_in[11];
    const float* b_ih = (const float*)d_in[12];
    const float* W_ic = (const float*)d_in[13];
    const float* b_ic = (const float*)d_in[14];
    const float* W_fh = (const float*)d_in[15];
    const float* b_fh = (const float*)d_in[16];
    const float* W_fc = (const float*)d_in[17];
    const float* b_fc = (const float*)d_in[18];
    const float* W_ch = (const float*)d_in[19];
    const float* b_ch = (const float*)d_in[20];
    const float* W_oh = (const float*)d_in[21];
    const float* b_oh = (const float*)d_in[22];
    const float* W_oc = (const float*)d_in[23];
    const float* b_oc = (const float*)d_in[24];
    float* out = (float*)d_out;

    cudaFuncSetAttribute(gemm_kernel, cudaFuncAttributeMaxDynamicSharedMemorySize, SMEM_DYN);

    pack_A1<<<2048, 256>>>(x, h, c);
    pack_W1<<<8192, 256>>>(W_ix, W_fx, W_cx, W_ox, W_ih, W_ic, W_fh, W_fc, W_ch, W_oh);
    pack_W2<<<1024, 256>>>(W_oc);

    dim3 g1(BB / BM, N1 / BN);   // 32 x 64
    gemm_kernel<<<g1, 256, SMEM_DYN>>>(0);

    ew1<<<4096, 256>>>(c, b_ix, b_ih, b_ic, b_fx, b_fh, b_fc, b_cx, b_ch, out);

    dim3 g2(BB / BM, HH / BN);   // 32 x 16
    gemm_kernel<<<g2, 256, SMEM_DYN>>>(1);

    ew2<<<4096, 256>>>(b_ox, b_oh, b_oc, out);
}

// round 13
// speedup vs baseline: 2.6810x; 1.0299x over previous
#include <cuda_runtime.h>
#include <cuda_fp16.h>
#include <cstdint>
#include <cstddef>
#include <math.h>

// ---------------- problem dims ----------------
#define BB 4096
#define HH 2048
#define K1 6144          // K for GEMM1: [x|h|c]
#define N1 8192          // N for GEMM1: 4 gates * 2048

// ---------------- GEMM tile config ----------------
#define BM 128
#define BN 128
#define BK 64            // fp16 elements per chunk (128B data per row)
#define ROWB 144         // smem row stride bytes (128 data + 16 pad)
#define A_TILE_BYTES (BM * ROWB)             // 18432
#define B_TILE_BYTES (BN * ROWB)             // 18432
#define ST_A 0
#define ST_B A_TILE_BYTES
#define STAGE_BYTES (A_TILE_BYTES + B_TILE_BYTES)           // 36864
#define NSTAGE 3
#define SMEM_DYN (NSTAGE * STAGE_BYTES + 128)               // 110720

// ---------------- device scratch (static; alloc APIs are forbidden) ------
__device__ __half g_A1[(size_t)BB * K1];
__device__ __half g_W1[(size_t)N1 * K1];
__device__ __half g_W2[(size_t)HH * HH];
__device__ __half g_A2[(size_t)BB * HH];
__device__ float  g_C[(size_t)BB * N1];

// ---------------- helpers ----------------
__device__ __forceinline__ uint32_t smem_u32(const void* p) {
    uint32_t a;
    asm("{ .reg .u64 t; cvta.to.shared.u64 t, %1; cvt.u32.u64 %0, t; }" : "=r"(a) : "l"(p));
    return a;
}

__device__ __forceinline__ void cp_async16(uint32_t dst, const void* src) {
    asm volatile("cp.async.cg.shared.global [%0], [%1], 16;" :: "r"(dst), "l"(src));
}

__device__ __forceinline__ void ldmatrix_x4(uint32_t* r, uint32_t addr) {
    asm volatile("ldmatrix.sync.aligned.m8n8.x4.shared.b16 {%0,%1,%2,%3}, [%4];"
        : "=r"(r[0]), "=r"(r[1]), "=r"(r[2]), "=r"(r[3]) : "r"(addr));
}

__device__ __forceinline__ void ldmatrix_x2(uint32_t* r, uint32_t addr) {
    asm volatile("ldmatrix.sync.aligned.m8n8.x2.shared.b16 {%0,%1}, [%2];"
        : "=r"(r[0]), "=r"(r[1]) : "r"(addr));
}

__device__ __forceinline__ void mma_16816(float* c, const uint32_t* a, const uint32_t* b) {
    asm volatile(
        "mma.sync.aligned.m16n8k16.row.col.f32.f16.f16.f32 "
        "{%0,%1,%2,%3}, {%4,%5,%6,%7}, {%8,%9}, {%0,%1,%2,%3};"
        : "+f"(c[0]), "+f"(c[1]), "+f"(c[2]), "+f"(c[3])
        : "r"(a[0]), "r"(a[1]), "r"(a[2]), "r"(a[3]), "r"(b[0]), "r"(b[1]));
}

// ---------------- packing kernels ----------------
__global__ void pack_A1(const float* __restrict__ x, const float* __restrict__ h,
                        const float* __restrict__ c) {
    size_t n = (size_t)BB * K1;
    for (size_t i = blockIdx.x * (size_t)blockDim.x + threadIdx.x; i < n;
         i += (size_t)gridDim.x * blockDim.x) {
        size_t m = i / K1;
        int k = (int)(i - m * K1);
        float v;
        if (k < HH)          v = x[m * HH + k];
        else if (k < 2 * HH) v = h[m * HH + (k - HH)];
        else                 v = c[m * HH + (k - 2 * HH)];
        g_A1[i] = __float2half_rn(v);
    }
}

__global__ void pack_W1(const float* __restrict__ Wix, const float* __restrict__ Wfx,
                        const float* __restrict__ Wcx, const float* __restrict__ Wox,
                        const float* __restrict__ Wih, const float* __restrict__ Wic,
                        const float* __restrict__ Wfh, const float* __restrict__ Wfc,
                        const float* __restrict__ Wch, const float* __restrict__ Woh) {
    size_t n = (size_t)N1 * K1;
    for (size_t i = blockIdx.x * (size_t)blockDim.x + threadIdx.x; i < n;
         i += (size_t)gridDim.x * blockDim.x) {
        size_t row = i / K1;
        int k = (int)(i - row * K1);
        int gate = (int)(row >> 11);
        int j = (int)(row & 2047);
        int seg = k >> 11;
        int kk = k & 2047;
        const float* W = nullptr;
        switch (gate * 3 + seg) {
            case 0:  W = Wix; break;
            case 1:  W = Wih; break;
            case 2:  W = Wic; break;
            case 3:  W = Wfx; break;
            case 4:  W = Wfh; break;
            case 5:  W = Wfc; break;
            case 6:  W = Wcx; break;
            case 7:  W = Wch; break;
            case 9:  W = Wox; break;
            case 10: W = Woh; break;
            default: break;   // gate g/o c-slot: zero (never read: variable-K skips it)
        }
        float v = W ? W[(size_t)j * HH + kk] : 0.0f;
        g_W1[i] = __float2half_rn(v);
    }
}

__global__ void pack_W2(const float* __restrict__ Woc) {
    size_t n = (size_t)HH * HH;
    for (size_t i = blockIdx.x * (size_t)blockDim.x + threadIdx.x; i < n;
         i += (size_t)gridDim.x * blockDim.x) {
        g_W2[i] = __float2half_rn(Woc[i]);
    }
}

// ---------------- GEMM: C = A*B^T (fp16 operands, fp32 accumulate) ----------
// cp.async 3-stage pipeline, BK=64, wait_group 1, one barrier per chunk.
// CTA tile 128x128, 8 warps as 2(M) x 4(N), warp tile 64x32, 2 CTAs/SM.
// Inner loop software-pipelined: fragments double-buffered across k-steps.
__global__ void __launch_bounds__(256, 2)
gemm_kernel(int which) {
    const __half *Ap, *Bp;
    float* C;
    int K, Keff;
    const size_t brow0 = (size_t)blockIdx.y * BN;
    if (which == 0) {
        Ap = g_A1; Bp = g_W1;
        C = g_C; K = K1;
        Keff = (brow0 >= 4096) ? 4096 : 6144;   // gates g,o have zero c-slot
    } else {
        Ap = g_A2; Bp = g_W2;
        C = g_C + 2 * HH;   // gate-g column region (already consumed by ew1)
        K = HH; Keff = HH;
    }
    const int ldc = N1;
    const size_t arow0 = (size_t)blockIdx.x * BM;
    const int nchunk = Keff / BK;
    const int tid = threadIdx.x;
    const int lane = tid & 31;
    const int wid = tid >> 5;
    const int warpM = wid & 1;   // 2 warps over M: 64 rows each
    const int warpN = wid >> 1;  // 4 warps over N: 32 cols each

    extern __shared__ char dsmem[];
    const uint32_t sb = (smem_u32(dsmem) + 127u) & ~127u;

    // loader for chunk j into stage s (always commits, possibly empty group)
    auto load_chunk = [&](int j, int s) {
        if (j < nchunk) {
            const uint32_t stage = sb + s * STAGE_BYTES;
            const size_t kof = (size_t)j * BK;
            #pragma unroll
            for (int it = 0; it < 8; ++it) {
                int idx = tid + it * 256;        // 0..2047
                int g = idx & 7;                 // 16B segment within 128B row
                int rs = idx >> 3;               // 0..255: tile-row id
                const __half* src;
                uint32_t dstbase;
                int r;
                if (rs < 128) { r = rs;       src = Ap + (arow0 + r) * K + kof; dstbase = stage + ST_A; }
                else          { r = rs - 128; src = Bp + (brow0 + r) * K + kof; dstbase = stage + ST_B; }
                uint32_t dst = dstbase + (uint32_t)r * ROWB + (uint32_t)g * 16u;
                cp_async16(dst, (const void*)(src + g * 8));
            }
        }
        asm volatile("cp.async.commit_group;" ::: "memory");
    };

    float acc[4][4][4];
    #pragma unroll
    for (int mi = 0; mi < 4; ++mi)
        #pragma unroll
        for (int ni = 0; ni < 4; ++ni)
            #pragma unroll
            for (int q = 0; q < 4; ++q) acc[mi][ni][q] = 0.0f;

    load_chunk(0, 0);
    load_chunk(1, 1);

    // fragment double buffers
    uint32_t aR[2][4][4];
    uint32_t bR[2][4][2];

    for (int j = 0; j < nchunk; ++j) {
        const int s = j % NSTAGE;
        // chunk j ready (j+1 may be in flight); recycle slot (j+2)%3.
        asm volatile("cp.async.wait_group 1;" ::: "memory");
        __syncthreads();          // all warps done with compute(j-1) -> slot (j+2)%3 free
        load_chunk(j + 2, (j + 2) % NSTAGE);

        const uint32_t stage = sb + s * STAGE_BYTES;
        // A: ldmatrix.x4 address — lanes 0..15 rows, 16..31 rows at +16B
        const uint32_t a_0 = stage + ST_A + (warpM * 64 + (lane & 15)) * ROWB + (lane >> 4) * 16;
        // B: ldmatrix.x2 address — lanes 0..7 rows at koff, lanes 8..15 at +16B
        const uint32_t b_0 = stage + ST_B + (warpN * 32 + (lane & 7)) * ROWB + ((lane >> 3) & 1) * 16;

        // prologue: fragments for ks=0
        #pragma unroll
        for (int mi = 0; mi < 4; ++mi)
            ldmatrix_x4(aR[0][mi], a_0 + mi * 16 * ROWB);
        #pragma unroll
        for (int ni = 0; ni < 4; ++ni)
            ldmatrix_x2(bR[0][ni], b_0 + ni * 8 * ROWB);

        #pragma unroll
        for (int ks = 0; ks < 4; ++ks) {
            const int cur = ks & 1;
            if (ks < 3) {
                const uint32_t koff = (ks + 1) * 32;
                #pragma unroll
                for (int mi = 0; mi < 4; ++mi)
                    ldmatrix_x4(aR[cur ^ 1][mi], a_0 + mi * 16 * ROWB + koff);
                #pragma unroll
                for (int ni = 0; ni < 4; ++ni)
                    ldmatrix_x2(bR[cur ^ 1][ni], b_0 + ni * 8 * ROWB + koff);
            }
            #pragma unroll
            for (int ni = 0; ni < 4; ++ni)
                #pragma unroll
                for (int mi = 0; mi < 4; ++mi)
                    mma_16816(acc[mi][ni], aR[cur][mi], bR[cur][ni]);
        }
    }

    // epilogue: fp32 store
    #pragma unroll
    for (int mi = 0; mi < 4; ++mi) {
        const size_t m0 = arow0 + warpM * 64 + mi * 16 + (lane >> 2);
        #pragma unroll
        for (int ni = 0; ni < 4; ++ni) {
            const size_t n0 = brow0 + warpN * 32 + ni * 8 + (lane & 3) * 2;
            float2 v0 = make_float2(acc[mi][ni][0], acc[mi][ni][1]);
            float2 v1 = make_float2(acc[mi][ni][2], acc[mi][ni][3]);
            *reinterpret_cast<float2*>(C + m0 * ldc + n0)       = v0;
            *reinterpret_cast<float2*>(C + (m0 + 8) * ldc + n0) = v1;
        }
    }
}

// ---------------- elementwise 1: gates i,f,g -> c_next; pack A2 -------------
__global__ void ew1(const float* __restrict__ c,
                    const float* __restrict__ b_ix, const float* __restrict__ b_ih,
                    const float* __restrict__ b_ic,
                    const float* __restrict__ b_fx, const float* __restrict__ b_fh,
                    const float* __restrict__ b_fc,
                    const float* __restrict__ b_cx, const float* __restrict__ b_ch,
                    float* __restrict__ out) {
    const size_t n = (size_t)BB * HH;
    for (size_t i = blockIdx.x * (size_t)blockDim.x + threadIdx.x; i < n;
         i += (size_t)gridDim.x * blockDim.x) {
        size_t m = i / HH;
        int j = (int)(i - m * HH);
        const float* crow = g_C + m * (size_t)N1;
        float ip = crow[j]        + b_ix[j] + b_ih[j] + b_ic[j];
        float fp = crow[2048 + j] + b_fx[j] + b_fh[j] + b_fc[j];
        float gp = crow[4096 + j] + b_cx[j] + b_ch[j];
        float ii = 1.0f / (1.0f + expf(-ip));
        float ff = 1.0f / (1.0f + expf(-fp));
        float gg = tanhf(gp);
        float cn = ff * c[i] + ii * gg;
        out[2 * n + i] = cn;                       // c_next
        g_A2[i] = __float2half_rn(cn);             // A2 for GEMM2
    }
}

// ---------------- elementwise 2: o gate, h_next ----------------
__global__ void ew2(const float* __restrict__ b_ox, const float* __restrict__ b_oh,
                    const float* __restrict__ b_oc,
                    float* __restrict__ out) {
    const size_t n = (size_t)BB * HH;
    for (size_t i = blockIdx.x * (size_t)blockDim.x + threadIdx.x; i < n;
         i += (size_t)gridDim.x * blockDim.x) {
        size_t m = i / HH;
        int j = (int)(i - m * HH);
        const float* crow = g_C + m * (size_t)N1;
        float op = crow[6144 + j] + crow[4096 + j] + b_ox[j] + b_oh[j] + b_oc[j];
        float cn = out[2 * n + i];
        float t = tanhf(cn);
        float o = (1.0f / (1.0f + expf(-op))) * t;
        out[i] = o;           // o
        out[n + i] = o * t;   // h_next
    }
}

// ---------------- launch ----------------
extern "C" void kernel_launch(void* const* d_in, const int* in_sizes, int n_in,
                              void* d_out, int out_size) {
    const float* x    = (const float*)d_in[0];
    const float* h    = (const float*)d_in[1];
    const float* c    = (const float*)d_in[2];
    const float* W_ix = (const float*)d_in[3];
    const float* b_ix = (const float*)d_in[4];
    const float* W_fx = (const float*)d_in[5];
    const float* b_fx = (const float*)d_in[6];
    const float* W_cx = (const float*)d_in[7];
    const float* b_cx = (const float*)d_in[8];
    const float* W_ox = (const float*)d_in[9];
    const float* b_ox = (const float*)d_in[10];
    const float* W_ih = (const float*)d_in[11];
    const float* b_ih = (const float*)d_in[12];
    const float* W_ic = (const float*)d_in[13];
    const float* b_ic = (const float*)d_in[14];
    const float* W_fh = (const float*)d_in[15];
    const float* b_fh = (const float*)d_in[16];
    const float* W_fc = (const float*)d_in[17];
    const float* b_fc = (const float*)d_in[18];
    const float* W_ch = (const float*)d_in[19];
    const float* b_ch = (const float*)d_in[20];
    const float* W_oh = (const float*)d_in[21];
    const float* b_oh = (const float*)d_in[22];
    const float* W_oc = (const float*)d_in[23];
    const float* b_oc = (const float*)d_in[24];
    float* out = (float*)d_out;

    cudaFuncSetAttribute(gemm_kernel, cudaFuncAttributeMaxDynamicSharedMemorySize, SMEM_DYN);

    pack_A1<<<2048, 256>>>(x, h, c);
    pack_W1<<<8192, 256>>>(W_ix, W_fx, W_cx, W_ox, W_ih, W_ic, W_fh, W_fc, W_ch, W_oh);
    pack_W2<<<1024, 256>>>(W_oc);

    dim3 g1(BB / BM, N1 / BN);   // 32 x 64
    gemm_kernel<<<g1, 256, SMEM_DYN>>>(0);

    ew1<<<4096, 256>>>(c, b_ix, b_ih, b_ic, b_fx, b_fh, b_fc, b_cx, b_ch, out);

    dim3 g2(BB / BM, HH / BN);   // 32 x 16
    gemm_kernel<<<g2, 256, SMEM_DYN>>>(1);

    ew2<<<4096, 256>>>(b_ox, b_oh, b_oc, out);
}

// round 14
// speedup vs baseline: 3.0285x; 1.1296x over previous
#include <cuda_runtime.h>
#include <cuda_fp16.h>
#include <cstdint>
#include <cstddef>
#include <math.h>

// ---------------- problem dims ----------------
#define BB 4096
#define HH 2048
#define K1 6144          // K for GEMM1: [x|h|c]
#define N1 8192          // N for GEMM1: 4 gates * 2048

// ---------------- GEMM tile config ----------------
#define BM 128
#define BN 128
#define BK 64            // fp16 elements per chunk (128B data per row)
#define ROWB 144         // smem row stride bytes (128 data + 16 pad)
#define A_TILE_BYTES (BM * ROWB)             // 18432
#define B_TILE_BYTES (BN * ROWB)             // 18432
#define ST_A 0
#define ST_B A_TILE_BYTES
#define STAGE_BYTES (A_TILE_BYTES + B_TILE_BYTES)           // 36864
#define NSTAGE 3
#define SMEM_DYN (NSTAGE * STAGE_BYTES + 128)               // 110720

// ---------------- device scratch (static; alloc APIs are forbidden) ------
__device__ __half g_A1[(size_t)BB * K1];
__device__ __half g_W1[(size_t)N1 * K1];
__device__ __half g_W2[(size_t)HH * HH];
__device__ __half g_A2[(size_t)BB * HH];
__device__ float  g_C[(size_t)BB * N1];

// ---------------- helpers ----------------
__device__ __forceinline__ uint32_t smem_u32(const void* p) {
    uint32_t a;
    asm("{ .reg .u64 t; cvta.to.shared.u64 t, %1; cvt.u32.u64 %0, t; }" : "=r"(a) : "l"(p));
    return a;
}

__device__ __forceinline__ void cp_async16(uint32_t dst, const void* src) {
    asm volatile("cp.async.cg.shared.global [%0], [%1], 16;" :: "r"(dst), "l"(src));
}

__device__ __forceinline__ void ldmatrix_x4(uint32_t* r, uint32_t addr) {
    asm volatile("ldmatrix.sync.aligned.m8n8.x4.shared.b16 {%0,%1,%2,%3}, [%4];"
        : "=r"(r[0]), "=r"(r[1]), "=r"(r[2]), "=r"(r[3]) : "r"(addr));
}

__device__ __forceinline__ void ldmatrix_x2(uint32_t* r, uint32_t addr) {
    asm volatile("ldmatrix.sync.aligned.m8n8.x2.shared.b16 {%0,%1}, [%2];"
        : "=r"(r[0]), "=r"(r[1]) : "r"(addr));
}

__device__ __forceinline__ void mma_16816(float* c, const uint32_t* a, const uint32_t* b) {
    asm volatile(
        "mma.sync.aligned.m16n8k16.row.col.f32.f16.f16.f32 "
        "{%0,%1,%2,%3}, {%4,%5,%6,%7}, {%8,%9}, {%0,%1,%2,%3};"
        : "+f"(c[0]), "+f"(c[1]), "+f"(c[2]), "+f"(c[3])
        : "r"(a[0]), "r"(a[1]), "r"(a[2]), "r"(a[3]), "r"(b[0]), "r"(b[1]));
}

// fast activations (__expf: ~1e-6 rel err, negligible vs fp16 GEMM error)
__device__ __forceinline__ float sigmoid_f(float x) { return 1.0f / (1.0f + __expf(-x)); }
__device__ __forceinline__ float tanh_f(float x)    { return 2.0f / (1.0f + __expf(-2.0f * x)) - 1.0f; }

// convert 8 floats (2x float4) -> uint4 of 8 halves
__device__ __forceinline__ uint4 pack8(const float4 a, const float4 b) {
    uint4 r;
    __half2 h0 = __floats2half2_rn(a.x, a.y);
    __half2 h1 = __floats2half2_rn(a.z, a.w);
    __half2 h2 = __floats2half2_rn(b.x, b.y);
    __half2 h3 = __floats2half2_rn(b.z, b.w);
    r.x = *reinterpret_cast<uint32_t*>(&h0);
    r.y = *reinterpret_cast<uint32_t*>(&h1);
    r.z = *reinterpret_cast<uint32_t*>(&h2);
    r.w = *reinterpret_cast<uint32_t*>(&h3);
    return r;
}

// ---------------- packing kernels (8 elements / thread) ----------------
__global__ void pack_A1(const float* __restrict__ x, const float* __restrict__ h,
                        const float* __restrict__ c) {
    const int tid = blockIdx.x * 256 + threadIdx.x;        // 0 .. BB*K1/8-1
    const int m = tid / (K1 / 8);
    const int k = (tid - m * (K1 / 8)) * 8;
    const float* src;
    if (k < HH)          src = x + (size_t)m * HH + k;
    else if (k < 2 * HH) src = h + (size_t)m * HH + (k - HH);
    else                 src = c + (size_t)m * HH + (k - 2 * HH);
    float4 a = *reinterpret_cast<const float4*>(src);
    float4 b = *reinterpret_cast<const float4*>(src + 4);
    *reinterpret_cast<uint4*>(g_A1 + (size_t)m * K1 + k) = pack8(a, b);
}

__global__ void pack_W1(const float* __restrict__ Wix, const float* __restrict__ Wfx,
                        const float* __restrict__ Wcx, const float* __restrict__ Wox,
                        const float* __restrict__ Wih, const float* __restrict__ Wic,
                        const float* __restrict__ Wfh, const float* __restrict__ Wfc,
                        const float* __restrict__ Wch, const float* __restrict__ Woh) {
    const int tid = blockIdx.x * 256 + threadIdx.x;        // 0 .. N1*K1/8-1
    const int row = tid / (K1 / 8);
    const int k = (tid - row * (K1 / 8)) * 8;
    const int gate = row >> 11;
    const int j = row & 2047;
    const int seg = k >> 11;
    const int kk = k & 2047;
    const float* W = nullptr;
    switch (gate * 3 + seg) {
        case 0:  W = Wix; break;
        case 1:  W = Wih; break;
        case 2:  W = Wic; break;
        case 3:  W = Wfx; break;
        case 4:  W = Wfh; break;
        case 5:  W = Wfc; break;
        case 6:  W = Wcx; break;
        case 7:  W = Wch; break;
        case 9:  W = Wox; break;
        case 10: W = Woh; break;
        default: break;   // gate g/o c-slot: zero (never read: variable-K skips it)
    }
    uint4 out;
    if (W) {
        const float* src = W + (size_t)j * HH + kk;
        float4 a = *reinterpret_cast<const float4*>(src);
        float4 b = *reinterpret_cast<const float4*>(src + 4);
        out = pack8(a, b);
    } else {
        out = make_uint4(0, 0, 0, 0);
    }
    *reinterpret_cast<uint4*>(g_W1 + (size_t)row * K1 + k) = out;
}

__global__ void pack_W2(const float* __restrict__ Woc) {
    const int tid = blockIdx.x * 256 + threadIdx.x;        // 0 .. HH*HH/8-1
    const size_t i = (size_t)tid * 8;
    float4 a = *reinterpret_cast<const float4*>(Woc + i);
    float4 b = *reinterpret_cast<const float4*>(Woc + i + 4);
    *reinterpret_cast<uint4*>(g_W2 + i) = pack8(a, b);
}

// ---------------- GEMM: C = A*B^T (fp16 operands, fp32 accumulate) ----------
// cp.async 3-stage pipeline, BK=64, wait_group 1, one barrier per chunk.
// CTA tile 128x128, 8 warps as 2(M) x 4(N), warp tile 64x32, 2 CTAs/SM.
// Inner loop software-pipelined: fragments double-buffered across k-steps.
__global__ void __launch_bounds__(256, 2)
gemm_kernel(int which) {
    const __half *Ap, *Bp;
    float* C;
    int K, Keff;
    const size_t brow0 = (size_t)blockIdx.y * BN;
    if (which == 0) {
        Ap = g_A1; Bp = g_W1;
        C = g_C; K = K1;
        Keff = (brow0 >= 4096) ? 4096 : 6144;   // gates g,o have zero c-slot
    } else {
        Ap = g_A2; Bp = g_W2;
        C = g_C + 2 * HH;   // gate-g column region (already consumed by ew1)
        K = HH; Keff = HH;
    }
    const int ldc = N1;
    const size_t arow0 = (size_t)blockIdx.x * BM;
    const int nchunk = Keff / BK;
    const int tid = threadIdx.x;
    const int lane = tid & 31;
    const int wid = tid >> 5;
    const int warpM = wid & 1;   // 2 warps over M: 64 rows each
    const int warpN = wid >> 1;  // 4 warps over N: 32 cols each

    extern __shared__ char dsmem[];
    const uint32_t sb = (smem_u32(dsmem) + 127u) & ~127u;

    // loader for chunk j into stage s (always commits, possibly empty group)
    auto load_chunk = [&](int j, int s) {
        if (j < nchunk) {
            const uint32_t stage = sb + s * STAGE_BYTES;
            const size_t kof = (size_t)j * BK;
            #pragma unroll
            for (int it = 0; it < 8; ++it) {
                int idx = tid + it * 256;        // 0..2047
                int g = idx & 7;                 // 16B segment within 128B row
                int rs = idx >> 3;               // 0..255: tile-row id
                const __half* src;
                uint32_t dstbase;
                int r;
                if (rs < 128) { r = rs;       src = Ap + (arow0 + r) * K + kof; dstbase = stage + ST_A; }
                else          { r = rs - 128; src = Bp + (brow0 + r) * K + kof; dstbase = stage + ST_B; }
                uint32_t dst = dstbase + (uint32_t)r * ROWB + (uint32_t)g * 16u;
                cp_async16(dst, (const void*)(src + g * 8));
            }
        }
        asm volatile("cp.async.commit_group;" ::: "memory");
    };

    float acc[4][4][4];
    #pragma unroll
    for (int mi = 0; mi < 4; ++mi)
        #pragma unroll
        for (int ni = 0; ni < 4; ++ni)
            #pragma unroll
            for (int q = 0; q < 4; ++q) acc[mi][ni][q] = 0.0f;

    load_chunk(0, 0);
    load_chunk(1, 1);

    // fragment double buffers
    uint32_t aR[2][4][4];
    uint32_t bR[2][4][2];

    for (int j = 0; j < nchunk; ++j) {
        const int s = j % NSTAGE;
        // chunk j ready (j+1 may be in flight); recycle slot (j+2)%3.
        asm volatile("cp.async.wait_group 1;" ::: "memory");
        __syncthreads();          // all warps done with compute(j-1) -> slot (j+2)%3 free
        load_chunk(j + 2, (j + 2) % NSTAGE);

        const uint32_t stage = sb + s * STAGE_BYTES;
        // A: ldmatrix.x4 address — lanes 0..15 rows, 16..31 rows at +16B
        const uint32_t a_0 = stage + ST_A + (warpM * 64 + (lane & 15)) * ROWB + (lane >> 4) * 16;
        // B: ldmatrix.x2 address — lanes 0..7 rows at koff, lanes 8..15 at +16B
        const uint32_t b_0 = stage + ST_B + (warpN * 32 + (lane & 7)) * ROWB + ((lane >> 3) & 1) * 16;

        // prologue: fragments for ks=0
        #pragma unroll
        for (int mi = 0; mi < 4; ++mi)
            ldmatrix_x4(aR[0][mi], a_0 + mi * 16 * ROWB);
        #pragma unroll
        for (int ni = 0; ni < 4; ++ni)
            ldmatrix_x2(bR[0][ni], b_0 + ni * 8 * ROWB);

        #pragma unroll
        for (int ks = 0; ks < 4; ++ks) {
            const int cur = ks & 1;
            if (ks < 3) {
                const uint32_t koff = (ks + 1) * 32;
                #pragma unroll
                for (int mi = 0; mi < 4; ++mi)
                    ldmatrix_x4(aR[cur ^ 1][mi], a_0 + mi * 16 * ROWB + koff);
                #pragma unroll
                for (int ni = 0; ni < 4; ++ni)
                    ldmatrix_x2(bR[cur ^ 1][ni], b_0 + ni * 8 * ROWB + koff);
            }
            #pragma unroll
            for (int ni = 0; ni < 4; ++ni)
                #pragma unroll
                for (int mi = 0; mi < 4; ++mi)
                    mma_16816(acc[mi][ni], aR[cur][mi], bR[cur][ni]);
        }
    }

    // epilogue: fp32 store
    #pragma unroll
    for (int mi = 0; mi < 4; ++mi) {
        const size_t m0 = arow0 + warpM * 64 + mi * 16 + (lane >> 2);
        #pragma unroll
        for (int ni = 0; ni < 4; ++ni) {
            const size_t n0 = brow0 + warpN * 32 + ni * 8 + (lane & 3) * 2;
            float2 v0 = make_float2(acc[mi][ni][0], acc[mi][ni][1]);
            float2 v1 = make_float2(acc[mi][ni][2], acc[mi][ni][3]);
            *reinterpret_cast<float2*>(C + m0 * ldc + n0)       = v0;
            *reinterpret_cast<float2*>(C + (m0 + 8) * ldc + n0) = v1;
        }
    }
}

// ---------------- elementwise 1 (4 elems/thread): gates -> c_next; pack A2 --
__global__ void ew1(const float* __restrict__ c,
                    const float* __restrict__ b_ix, const float* __restrict__ b_ih,
                    const float* __restrict__ b_ic,
                    const float* __restrict__ b_fx, const float* __restrict__ b_fh,
                    const float* __restrict__ b_fc,
                    const float* __restrict__ b_cx, const float* __restrict__ b_ch,
                    float* __restrict__ out) {
    const size_t n = (size_t)BB * HH;
    const int tid = blockIdx.x * 256 + threadIdx.x;        // 0 .. BB*HH/4-1
    const int m = tid / (HH / 4);
    const int j = (tid - m * (HH / 4)) * 4;
    const float* crow = g_C + (size_t)m * N1;

    float4 iv = *reinterpret_cast<const float4*>(crow + j);
    float4 fv = *reinterpret_cast<const float4*>(crow + 2048 + j);
    float4 gv = *reinterpret_cast<const float4*>(crow + 4096 + j);
    float4 cv = *reinterpret_cast<const float4*>(c + (size_t)m * HH + j);
    float4 bix = *reinterpret_cast<const float4*>(b_ix + j);
    float4 bih = *reinterpret_cast<const float4*>(b_ih + j);
    float4 bic = *reinterpret_cast<const float4*>(b_ic + j);
    float4 bfx = *reinterpret_cast<const float4*>(b_fx + j);
    float4 bfh = *reinterpret_cast<const float4*>(b_fh + j);
    float4 bfc = *reinterpret_cast<const float4*>(b_fc + j);
    float4 bcx = *reinterpret_cast<const float4*>(b_cx + j);
    float4 bch = *reinterpret_cast<const float4*>(b_ch + j);

    float cn[4];
    {
        float ii, ff, gg;
        ii = sigmoid_f(iv.x + bix.x + bih.x + bic.x);
        ff = sigmoid_f(fv.x + bfx.x + bfh.x + bfc.x);
        gg = tanh_f(gv.x + bcx.x + bch.x);
        cn[0] = ff * cv.x + ii * gg;
        ii = sigmoid_f(iv.y + bix.y + bih.y + bic.y);
        ff = sigmoid_f(fv.y + bfx.y + bfh.y + bfc.y);
        gg = tanh_f(gv.y + bcx.y + bch.y);
        cn[1] = ff * cv.y + ii * gg;
        ii = sigmoid_f(iv.z + bix.z + bih.z + bic.z);
        ff = sigmoid_f(fv.z + bfx.z + bfh.z + bfc.z);
        gg = tanh_f(gv.z + bcx.z + bch.z);
        cn[2] = ff * cv.z + ii * gg;
        ii = sigmoid_f(iv.w + bix.w + bih.w + bic.w);
        ff = sigmoid_f(fv.w + bfx.w + bfh.w + bfc.w);
        gg = tanh_f(gv.w + bcx.w + bch.w);
        cn[3] = ff * cv.w + ii * gg;
    }
    const size_t base = (size_t)m * HH + j;
    *reinterpret_cast<float4*>(out + 2 * n + base) = make_float4(cn[0], cn[1], cn[2], cn[3]);
    __half2 h0 = __floats2half2_rn(cn[0], cn[1]);
    __half2 h1 = __floats2half2_rn(cn[2], cn[3]);
    uint2 hp;
    hp.x = *reinterpret_cast<uint32_t*>(&h0);
    hp.y = *reinterpret_cast<uint32_t*>(&h1);
    *reinterpret_cast<uint2*>(g_A2 + base) = hp;
}

// ---------------- elementwise 2 (4 elems/thread): o gate, h_next -----------
__global__ void ew2(const float* __restrict__ b_ox, const float* __restrict__ b_oh,
                    const float* __restrict__ b_oc,
                    float* __restrict__ out) {
    const size_t n = (size_t)BB * HH;
    const int tid = blockIdx.x * 256 + threadIdx.x;        // 0 .. BB*HH/4-1
    const int m = tid / (HH / 4);
    const int j = (tid - m * (HH / 4)) * 4;
    const float* crow = g_C + (size_t)m * N1;

    float4 op1 = *reinterpret_cast<const float4*>(crow + 6144 + j);   // x*Wox + h*Woh
    float4 op2 = *reinterpret_cast<const float4*>(crow + 4096 + j);   // c_next*Woc
    float4 box = *reinterpret_cast<const float4*>(b_ox + j);
    float4 boh = *reinterpret_cast<const float4*>(b_oh + j);
    float4 boc = *reinterpret_cast<const float4*>(b_oc + j);
    const size_t base = (size_t)m * HH + j;
    float4 cnv = *reinterpret_cast<const float4*>(out + 2 * n + base);

    float o[4], hn[4];
    {
        float t, s;
        t = tanh_f(cnv.x); s = sigmoid_f(op1.x + op2.x + box.x + boh.x + boc.x);
        o[0] = s * t; hn[0] = o[0] * t;
        t = tanh_f(cnv.y); s = sigmoid_f(op1.y + op2.y + box.y + boh.y + boc.y);
        o[1] = s * t; hn[1] = o[1] * t;
        t = tanh_f(cnv.z); s = sigmoid_f(op1.z + op2.z + box.z + boh.z + boc.z);
        o[2] = s * t; hn[2] = o[2] * t;
        t = tanh_f(cnv.w); s = sigmoid_f(op1.w + op2.w + box.w + boh.w + boc.w);
        o[3] = s * t; hn[3] = o[3] * t;
    }
    *reinterpret_cast<float4*>(out + base)     = make_float4(o[0], o[1], o[2], o[3]);
    *reinterpret_cast<float4*>(out + n + base) = make_float4(hn[0], hn[1], hn[2], hn[3]);
}

// ---------------- launch ----------------
extern "C" void kernel_launch(void* const* d_in, const int* in_sizes, int n_in,
                              void* d_out, int out_size) {
    const float* x    = (const float*)d_in[0];
    const float* h    = (const float*)d_in[1];
    const float* c    = (const float*)d_in[2];
    const float* W_ix = (const float*)d_in[3];
    const float* b_ix = (const float*)d_in[4];
    const float* W_fx = (const float*)d_in[5];
    const float* b_fx = (const float*)d_in[6];
    const float* W_cx = (const float*)d_in[7];
    const float* b_cx = (const float*)d_in[8];
    const float* W_ox = (const float*)d_in[9];
    const float* b_ox = (const float*)d_in[10];
    const float* W_ih = (const float*)d_in[11];
    const float* b_ih = (const float*)d_in[12];
    const float* W_ic = (const float*)d_in[13];
    const float* b_ic = (const float*)d_in[14];
    const float* W_fh = (const float*)d_in[15];
    const float* b_fh = (const float*)d_in[16];
    const float* W_fc = (const float*)d_in[17];
    const float* b_fc = (const float*)d_in[18];
    const float* W_ch = (const float*)d_in[19];
    const float* b_ch = (const float*)d_in[20];
    const float* W_oh = (const float*)d_in[21];
    const float* b_oh = (const float*)d_in[22];
    const float* W_oc = (const float*)d_in[23];
    const float* b_oc = (const float*)d_in[24];
    float* out = (float*)d_out;

    cudaFuncSetAttribute(gemm_kernel, cudaFuncAttributeMaxDynamicSharedMemorySize, SMEM_DYN);

    pack_A1<<<(BB * K1 / 8) / 256, 256>>>(x, h, c);                       // 12288 blocks
    pack_W1<<<((size_t)N1 * K1 / 8) / 256, 256>>>(W_ix, W_fx, W_cx, W_ox, W_ih, W_ic,
                                                  W_fh, W_fc, W_ch, W_oh); // 24576 blocks
    pack_W2<<<(HH * HH / 8) / 256, 256>>>(W_oc);                          // 2048 blocks

    dim3 g1(BB / BM, N1 / BN);   // 32 x 64
    gemm_kernel<<<g1, 256, SMEM_DYN>>>(0);

    ew1<<<(BB * HH / 4) / 256, 256>>>(c, b_ix, b_ih, b_ic, b_fx, b_fh, b_fc, b_cx, b_ch, out);

    dim3 g2(BB / BM, HH / BN);   // 32 x 16
    gemm_kernel<<<g2, 256, SMEM_DYN>>>(1);

    ew2<<<(BB * HH / 4) / 256, 256>>>(b_ox, b_oh, b_oc, out);
}